// round 1
// baseline (speedup 1.0000x reference)
#include <cuda_runtime.h>

#define N_NODES 20000
#define N_EDGES 320000
#define C_DIM   256
#define H_HEADS 8
#define D_HEAD  32
#define L_LAYERS 5
#define T_DIM   64
#define MS_SLOTS 10
#define MD_DIM  128
#define NEG_SLOPE 0.2f

// ---------------- scratch buffers (static device globals; no allocs allowed) --
__device__ float g_nodeA[N_NODES * C_DIM];
__device__ float g_nodeB[N_NODES * C_DIM];
__device__ float g_xt  [N_NODES * C_DIM];
__device__ float g_h   [N_NODES * C_DIM];
__device__ float g_q   [N_NODES * C_DIM];
__device__ float g_mid [N_NODES * C_DIM];
__device__ float g_es  [N_NODES * H_HEADS];
__device__ float g_ed  [N_NODES * H_HEADS];
__device__ float g_k   [MS_SLOTS * C_DIM];
__device__ float g_v   [MS_SLOTS * C_DIM];
__device__ float g_pool[C_DIM];
__device__ int   g_cnt   [N_NODES];
__device__ int   g_rowptr[N_NODES + 1];
__device__ int   g_cursor[N_NODES];
__device__ int   g_csrc  [N_EDGES];

// ---------------- small utility kernels --------------------------------------
__global__ void zero_int_kernel(int* p, int n) {
    int i = blockIdx.x * blockDim.x + threadIdx.x;
    if (i < n) p[i] = 0;
}
__global__ void zero_float_kernel(float* p, int n) {
    int i = blockIdx.x * blockDim.x + threadIdx.x;
    if (i < n) p[i] = 0.0f;
}

// ---------------- CSR build ---------------------------------------------------
__global__ void count_kernel(const int* __restrict__ dst, int* __restrict__ cnt) {
    int e = blockIdx.x * blockDim.x + threadIdx.x;
    if (e < N_EDGES) atomicAdd(&cnt[dst[e]], 1);
}

// single-block exclusive scan of g_cnt -> g_rowptr / g_cursor  (1024 threads)
__global__ void scan_kernel(const int* __restrict__ cnt,
                            int* __restrict__ rowptr, int* __restrict__ cursor) {
    const int PER = (N_NODES + 1023) / 1024;   // 20
    int tid = threadIdx.x;
    int s0 = tid * PER;
    int vals[PER];
    int local = 0;
#pragma unroll
    for (int k = 0; k < PER; k++) {
        int i = s0 + k;
        vals[k] = (i < N_NODES) ? cnt[i] : 0;
        local += vals[k];
    }
    int lane = tid & 31, w = tid >> 5;
    int x = local;
#pragma unroll
    for (int off = 1; off < 32; off <<= 1) {
        int t = __shfl_up_sync(0xFFFFFFFFu, x, off);
        if (lane >= off) x += t;
    }
    __shared__ int wsum[32];
    if (lane == 31) wsum[w] = x;
    __syncthreads();
    if (w == 0) {
        int y = wsum[lane];
#pragma unroll
        for (int off = 1; off < 32; off <<= 1) {
            int t = __shfl_up_sync(0xFFFFFFFFu, y, off);
            if (lane >= off) y += t;
        }
        wsum[lane] = y;
    }
    __syncthreads();
    int warpoff = (w > 0) ? wsum[w - 1] : 0;
    int excl = warpoff + x - local;
#pragma unroll
    for (int k = 0; k < PER; k++) {
        int i = s0 + k;
        if (i < N_NODES) { rowptr[i] = excl; cursor[i] = excl; }
        excl += vals[k];
    }
    if (tid == 1023) rowptr[N_NODES] = warpoff + x;   // == N_EDGES
}

__global__ void scatter_kernel(const int* __restrict__ src, const int* __restrict__ dst,
                               int* __restrict__ cursor, int* __restrict__ csrc) {
    int e = blockIdx.x * blockDim.x + threadIdx.x;
    if (e < N_EDGES) {
        int pos = atomicAdd(&cursor[dst[e]], 1);
        csrc[pos] = src[e];
    }
}

// ---------------- SGEMM: C = A[MxK] @ B[KxN]  (+ epilogue) --------------------
// epi: 0 = none, 1 = relu(C + bias[col]), 2 = C + R (elementwise residual)
#define BM 128
#define BN 128
#define BK 8
__global__ __launch_bounds__(256, 2)
void sgemm_kernel(const float* __restrict__ A, const float* __restrict__ B,
                  const float* __restrict__ R, const float* __restrict__ bias,
                  float* __restrict__ C, int M, int Nn, int K, int epi) {
    __shared__ float As[BK][BM];
    __shared__ float Bs[BK][BN];
    int tid = threadIdx.x;
    int bm = blockIdx.y * BM;
    int bn = blockIdx.x * BN;
    int arow = tid >> 1;
    int acol = (tid & 1) * 4;
    int brow = tid >> 5;
    int bcol = (tid & 31) * 4;
    int tx = tid & 15, ty = tid >> 4;

    float acc[8][8];
#pragma unroll
    for (int i = 0; i < 8; i++)
#pragma unroll
        for (int j = 0; j < 8; j++) acc[i][j] = 0.0f;

    for (int k0 = 0; k0 < K; k0 += BK) {
        float4 av = make_float4(0.f, 0.f, 0.f, 0.f);
        int gr = bm + arow;
        if (gr < M) av = *reinterpret_cast<const float4*>(&A[(size_t)gr * K + k0 + acol]);
        As[acol + 0][arow] = av.x;
        As[acol + 1][arow] = av.y;
        As[acol + 2][arow] = av.z;
        As[acol + 3][arow] = av.w;
        float4 bv = make_float4(0.f, 0.f, 0.f, 0.f);
        if (bn + bcol < Nn) bv = *reinterpret_cast<const float4*>(&B[(size_t)(k0 + brow) * Nn + bn + bcol]);
        *reinterpret_cast<float4*>(&Bs[brow][bcol]) = bv;
        __syncthreads();
#pragma unroll
        for (int kk = 0; kk < BK; kk++) {
            float4 a0 = *reinterpret_cast<float4*>(&As[kk][ty * 8]);
            float4 a1 = *reinterpret_cast<float4*>(&As[kk][ty * 8 + 4]);
            float4 b0 = *reinterpret_cast<float4*>(&Bs[kk][tx * 8]);
            float4 b1 = *reinterpret_cast<float4*>(&Bs[kk][tx * 8 + 4]);
            float ar[8] = {a0.x, a0.y, a0.z, a0.w, a1.x, a1.y, a1.z, a1.w};
            float br[8] = {b0.x, b0.y, b0.z, b0.w, b1.x, b1.y, b1.z, b1.w};
#pragma unroll
            for (int i = 0; i < 8; i++)
#pragma unroll
                for (int j = 0; j < 8; j++) acc[i][j] += ar[i] * br[j];
        }
        __syncthreads();
    }

#pragma unroll
    for (int i = 0; i < 8; i++) {
        int row = bm + ty * 8 + i;
        if (row >= M) continue;
        int col = bn + tx * 8;
        if (col >= Nn) continue;
        float out[8];
#pragma unroll
        for (int j = 0; j < 8; j++) out[j] = acc[i][j];
        if (epi == 1) {
#pragma unroll
            for (int j = 0; j < 8; j++) out[j] = fmaxf(out[j] + bias[col + j], 0.0f);
        } else if (epi == 2) {
            const float4* rp = reinterpret_cast<const float4*>(&R[(size_t)row * Nn + col]);
            float4 r0 = rp[0], r1 = rp[1];
            out[0] += r0.x; out[1] += r0.y; out[2] += r0.z; out[3] += r0.w;
            out[4] += r1.x; out[5] += r1.y; out[6] += r1.z; out[7] += r1.w;
        }
        float4* cp = reinterpret_cast<float4*>(&C[(size_t)row * Nn + col]);
        cp[0] = make_float4(out[0], out[1], out[2], out[3]);
        cp[1] = make_float4(out[4], out[5], out[6], out[7]);
    }
}

// ---------------- k/v projection (tiny): k[m][c] = sum_t mem[m][t]*Wk[t][c] ---
__global__ void kv_kernel(const float* __restrict__ mem, const float* __restrict__ Wk,
                          const float* __restrict__ Wv,
                          float* __restrict__ kout, float* __restrict__ vout) {
    __shared__ float sm[MS_SLOTS * MD_DIM];
    int m = blockIdx.x;          // 0..9
    int c = threadIdx.x;         // 0..255
    for (int i = threadIdx.x; i < MS_SLOTS * MD_DIM; i += blockDim.x) sm[i] = mem[i];
    __syncthreads();
    float ak = 0.f, av = 0.f;
    const float* mr = &sm[m * MD_DIM];
#pragma unroll 4
    for (int t = 0; t < MD_DIM; t++) {
        float mv = mr[t];
        ak += mv * Wk[t * C_DIM + c];
        av += mv * Wv[t * C_DIM + c];
    }
    kout[m * C_DIM + c] = ak;
    vout[m * C_DIM + c] = av;
}

// ---------------- e_src / e_dst ----------------------------------------------
__global__ void attn_vec_kernel(const float* __restrict__ h, const float* __restrict__ a_s,
                                const float* __restrict__ a_d,
                                float* __restrict__ es, float* __restrict__ ed) {
    __shared__ float sa[C_DIM], sd[C_DIM];
    for (int i = threadIdx.x; i < C_DIM; i += blockDim.x) { sa[i] = a_s[i]; sd[i] = a_d[i]; }
    __syncthreads();
    int idx = blockIdx.x * blockDim.x + threadIdx.x;   // n*8 + j
    if (idx >= N_NODES * H_HEADS) return;
    int n = idx >> 3, j = idx & 7;
    const float4* hr = reinterpret_cast<const float4*>(&h[(size_t)n * C_DIM + j * D_HEAD]);
    const float4* ar = reinterpret_cast<const float4*>(&sa[j * D_HEAD]);
    const float4* dr = reinterpret_cast<const float4*>(&sd[j * D_HEAD]);
    float accs = 0.f, accd = 0.f;
#pragma unroll
    for (int k = 0; k < 8; k++) {
        float4 hv = hr[k], avv = ar[k], dv = dr[k];
        accs += hv.x * avv.x + hv.y * avv.y + hv.z * avv.z + hv.w * avv.w;
        accd += hv.x * dv.x + hv.y * dv.y + hv.z * dv.z + hv.w * dv.w;
    }
    es[idx] = accs;
    ed[idx] = accd;
}

// ---------------- edge aggregation: warp per node, CSR softmax-aggregate ------
__global__ __launch_bounds__(256)
void edge_agg_kernel(const float* __restrict__ h, const int* __restrict__ rowptr,
                     const int* __restrict__ csrc, const float* __restrict__ es,
                     const float* __restrict__ ed, float* __restrict__ out) {
    __shared__ float sw[8][32][8];   // [warp][edge-in-chunk][head]
    __shared__ int   ss[8][32];
    int warp = threadIdx.x >> 5, lane = threadIdx.x & 31;
    int n = blockIdx.x * 8 + warp;
    if (n >= N_NODES) return;
    int beg = rowptr[n], end = rowptr[n + 1];

    float edn[8];
#pragma unroll
    for (int j = 0; j < 8; j++) edn[j] = ed[n * 8 + j];

    // pass 1: per-head max of leaky_relu(e_src[s] + e_dst[n])
    float mh[8];
#pragma unroll
    for (int j = 0; j < 8; j++) mh[j] = -1e30f;
    for (int i = beg + lane; i < end; i += 32) {
        int s = csrc[i];
#pragma unroll
        for (int j = 0; j < 8; j++) {
            float lg = es[s * 8 + j] + edn[j];
            lg = (lg > 0.f) ? lg : NEG_SLOPE * lg;
            mh[j] = fmaxf(mh[j], lg);
        }
    }
#pragma unroll
    for (int off = 16; off > 0; off >>= 1)
#pragma unroll
        for (int j = 0; j < 8; j++) mh[j] = fmaxf(mh[j], __shfl_xor_sync(0xFFFFFFFFu, mh[j], off));

    // pass 2: weights once per edge (staged in smem), accumulate msg + denom
    int head = lane >> 2;            // lane owns channels [lane*8, lane*8+8) -> head = lane/4
    float acc[8];
#pragma unroll
    for (int k = 0; k < 8; k++) acc[k] = 0.f;
    float dsum[8];
#pragma unroll
    for (int j = 0; j < 8; j++) dsum[j] = 0.f;

    for (int base = beg; base < end; base += 32) {
        int i = base + lane;
        int s = -1;
        float w[8];
        if (i < end) {
            s = csrc[i];
#pragma unroll
            for (int j = 0; j < 8; j++) {
                float lg = es[s * 8 + j] + edn[j];
                lg = (lg > 0.f) ? lg : NEG_SLOPE * lg;
                w[j] = __expf(lg - mh[j]);
                dsum[j] += w[j];
            }
        } else {
#pragma unroll
            for (int j = 0; j < 8; j++) w[j] = 0.f;
        }
        ss[warp][lane] = s;
#pragma unroll
        for (int j = 0; j < 8; j++) sw[warp][lane][j] = w[j];
        __syncwarp();
        int cnt = min(32, end - base);
        for (int e2 = 0; e2 < cnt; e2++) {
            int se = ss[warp][e2];
            float we = sw[warp][e2][head];
            const float4* hp = reinterpret_cast<const float4*>(&h[(size_t)se * C_DIM + lane * 8]);
            float4 h0 = hp[0], h1 = hp[1];
            acc[0] += we * h0.x; acc[1] += we * h0.y; acc[2] += we * h0.z; acc[3] += we * h0.w;
            acc[4] += we * h1.x; acc[5] += we * h1.y; acc[6] += we * h1.z; acc[7] += we * h1.w;
        }
        __syncwarp();
    }
#pragma unroll
    for (int off = 16; off > 0; off >>= 1)
#pragma unroll
        for (int j = 0; j < 8; j++) dsum[j] += __shfl_xor_sync(0xFFFFFFFFu, dsum[j], off);

    float inv = 1.0f / (dsum[head] + 1e-16f);
    float4 o0, o1;
    o0.x = fmaxf(acc[0] * inv, 0.f); o0.y = fmaxf(acc[1] * inv, 0.f);
    o0.z = fmaxf(acc[2] * inv, 0.f); o0.w = fmaxf(acc[3] * inv, 0.f);
    o1.x = fmaxf(acc[4] * inv, 0.f); o1.y = fmaxf(acc[5] * inv, 0.f);
    o1.z = fmaxf(acc[6] * inv, 0.f); o1.w = fmaxf(acc[7] * inv, 0.f);
    float4* op = reinterpret_cast<float4*>(&out[(size_t)n * C_DIM + lane * 8]);
    op[0] = o0; op[1] = o1;
}

// ---------------- memory cross-attention + residual + relu -------------------
__global__ __launch_bounds__(256)
void mem_attn_kernel(const float* __restrict__ q, const float* __restrict__ mid,
                     const float* __restrict__ xin, const float* __restrict__ kb,
                     const float* __restrict__ vb, float* __restrict__ out) {
    __shared__ float sk[MS_SLOTS][C_DIM];
    __shared__ float sv[MS_SLOTS][C_DIM];
    for (int i = threadIdx.x; i < MS_SLOTS * C_DIM; i += blockDim.x) {
        (&sk[0][0])[i] = kb[i];
        (&sv[0][0])[i] = vb[i];
    }
    __syncthreads();
    int warp = threadIdx.x >> 5, lane = threadIdx.x & 31;
    int n = blockIdx.x * 8 + warp;
    if (n >= N_NODES) return;

    const float4* qp = reinterpret_cast<const float4*>(&q[(size_t)n * C_DIM + lane * 8]);
    float4 q0 = qp[0], q1 = qp[1];
    float s[MS_SLOTS];
#pragma unroll
    for (int m = 0; m < MS_SLOTS; m++) {
        const float4* kp = reinterpret_cast<const float4*>(&sk[m][lane * 8]);
        float4 k0 = kp[0], k1 = kp[1];
        float p = q0.x * k0.x + q0.y * k0.y + q0.z * k0.z + q0.w * k0.w
                + q1.x * k1.x + q1.y * k1.y + q1.z * k1.z + q1.w * k1.w;
#pragma unroll
        for (int off = 16; off > 0; off >>= 1) p += __shfl_xor_sync(0xFFFFFFFFu, p, off);
        s[m] = p * 0.0625f;   // 1/sqrt(256)
    }
    float mx = s[0];
#pragma unroll
    for (int m = 1; m < MS_SLOTS; m++) mx = fmaxf(mx, s[m]);
    float sum = 0.f;
#pragma unroll
    for (int m = 0; m < MS_SLOTS; m++) { s[m] = __expf(s[m] - mx); sum += s[m]; }
    float invs = 1.0f / sum;

    const float4* mp = reinterpret_cast<const float4*>(&mid[(size_t)n * C_DIM + lane * 8]);
    const float4* xp = reinterpret_cast<const float4*>(&xin[(size_t)n * C_DIM + lane * 8]);
    float4 m0 = mp[0], m1 = mp[1], x0 = xp[0], x1 = xp[1];
    float acc[8] = {m0.x + x0.x, m0.y + x0.y, m0.z + x0.z, m0.w + x0.w,
                    m1.x + x1.x, m1.y + x1.y, m1.z + x1.z, m1.w + x1.w};
#pragma unroll
    for (int m = 0; m < MS_SLOTS; m++) {
        float a = s[m] * invs;
        const float4* vp = reinterpret_cast<const float4*>(&sv[m][lane * 8]);
        float4 v0 = vp[0], v1 = vp[1];
        acc[0] += a * v0.x; acc[1] += a * v0.y; acc[2] += a * v0.z; acc[3] += a * v0.w;
        acc[4] += a * v1.x; acc[5] += a * v1.y; acc[6] += a * v1.z; acc[7] += a * v1.w;
    }
    float4 o0 = make_float4(fmaxf(acc[0], 0.f), fmaxf(acc[1], 0.f), fmaxf(acc[2], 0.f), fmaxf(acc[3], 0.f));
    float4 o1 = make_float4(fmaxf(acc[4], 0.f), fmaxf(acc[5], 0.f), fmaxf(acc[6], 0.f), fmaxf(acc[7], 0.f));
    float4* op = reinterpret_cast<float4*>(&out[(size_t)n * C_DIM + lane * 8]);
    op[0] = o0; op[1] = o1;
}

// ---------------- pooling + final projection ----------------------------------
__global__ void pool_kernel(const float* __restrict__ node, float* __restrict__ pool) {
    int c = threadIdx.x;   // 256
    float acc = 0.f;
    for (int r = blockIdx.x; r < N_NODES; r += gridDim.x) acc += node[(size_t)r * C_DIM + c];
    atomicAdd(&pool[c], acc);
}

__global__ void final_kernel(const float* __restrict__ pool, const float* __restrict__ mem,
                             const float* __restrict__ Wc, const float* __restrict__ bc,
                             float* __restrict__ out) {
    __shared__ float s0[512], s1[512];
    int i = threadIdx.x;
    float val = 0.f;
    if (i < C_DIM) {
        val = pool[i] * (1.0f / (float)N_NODES);
    } else if (i < C_DIM + MD_DIM) {
        int t = i - C_DIM;
        float a = 0.f;
#pragma unroll
        for (int m = 0; m < MS_SLOTS; m++) a += mem[m * MD_DIM + t];
        val = a * (1.0f / (float)MS_SLOTS);
    }
    float c0 = 0.f, c1 = 0.f;
    if (i < C_DIM + MD_DIM) { c0 = val * Wc[i * 2 + 0]; c1 = val * Wc[i * 2 + 1]; }
    s0[i] = c0; s1[i] = c1;
    __syncthreads();
    for (int st = 256; st > 0; st >>= 1) {
        if (i < st) { s0[i] += s0[i + st]; s1[i] += s1[i + st]; }
        __syncthreads();
    }
    if (i == 0) { out[0] = s0[0] + bc[0]; out[1] = s1[0] + bc[1]; }
}

// ---------------- host launch -------------------------------------------------
static void* getsym(const void* symbol) {
    void* p = nullptr;
    cudaGetSymbolAddress(&p, symbol);
    return p;
}

extern "C" void kernel_launch(void* const* d_in, const int* in_sizes, int n_in,
                              void* d_out, int out_size) {
    const float* x    = (const float*)d_in[0];
    const int*   ei   = (const int*)  d_in[1];
    const float* te   = (const float*)d_in[2];
    const float* Wi   = (const float*)d_in[3];
    const float* bi   = (const float*)d_in[4];
    const float* Wg   = (const float*)d_in[5];
    const float* a_s  = (const float*)d_in[6];
    const float* a_d  = (const float*)d_in[7];
    const float* Wt   = (const float*)d_in[8];
    const float* Wq   = (const float*)d_in[9];
    const float* Wk   = (const float*)d_in[10];
    const float* Wv   = (const float*)d_in[11];
    const float* mem  = (const float*)d_in[12];
    const float* Wc   = (const float*)d_in[13];
    const float* bc   = (const float*)d_in[14];
    float* out = (float*)d_out;

    float* nodeA = (float*)getsym(g_nodeA);
    float* nodeB = (float*)getsym(g_nodeB);
    float* xt    = (float*)getsym(g_xt);
    float* hbuf  = (float*)getsym(g_h);
    float* qbuf  = (float*)getsym(g_q);
    float* midb  = (float*)getsym(g_mid);
    float* esb   = (float*)getsym(g_es);
    float* edb   = (float*)getsym(g_ed);
    float* kbuf  = (float*)getsym(g_k);
    float* vbuf  = (float*)getsym(g_v);
    float* pool  = (float*)getsym(g_pool);
    int* cnt     = (int*)getsym(g_cnt);
    int* rowptr  = (int*)getsym(g_rowptr);
    int* cursor  = (int*)getsym(g_cursor);
    int* csrc    = (int*)getsym(g_csrc);

    const int* src = ei;
    const int* dst = ei + N_EDGES;

    // CSR build
    zero_int_kernel<<<(N_NODES + 255) / 256, 256>>>(cnt, N_NODES);
    count_kernel<<<(N_EDGES + 255) / 256, 256>>>(dst, cnt);
    scan_kernel<<<1, 1024>>>(cnt, rowptr, cursor);
    scatter_kernel<<<(N_EDGES + 255) / 256, 256>>>(src, dst, cursor, csrc);

    dim3 gemm_grid(C_DIM / BN, (N_NODES + BM - 1) / BM);

    // input projection: nodeA = relu(x @ Wi + bi)
    sgemm_kernel<<<gemm_grid, 256>>>(x, Wi, nullptr, bi, nodeA, N_NODES, C_DIM, 128, 1);

    float* nin = nodeA;
    float* nout = nodeB;
    for (int l = 0; l < L_LAYERS; l++) {
        kv_kernel<<<MS_SLOTS, 256>>>(mem, Wk + (size_t)l * MD_DIM * C_DIM,
                                     Wv + (size_t)l * MD_DIM * C_DIM, kbuf, vbuf);
        // xt = nin + te @ Wt[l]
        sgemm_kernel<<<gemm_grid, 256>>>(te, Wt + (size_t)l * T_DIM * C_DIM, nin, nullptr,
                                         xt, N_NODES, C_DIM, T_DIM, 2);
        // h = xt @ Wg[l]
        sgemm_kernel<<<gemm_grid, 256>>>(xt, Wg + (size_t)l * C_DIM * C_DIM, nullptr, nullptr,
                                         hbuf, N_NODES, C_DIM, C_DIM, 0);
        attn_vec_kernel<<<(N_NODES * H_HEADS + 255) / 256, 256>>>(
            hbuf, a_s + l * H_HEADS * D_HEAD, a_d + l * H_HEADS * D_HEAD, esb, edb);
        edge_agg_kernel<<<(N_NODES + 7) / 8, 256>>>(hbuf, rowptr, csrc, esb, edb, midb);
        // q = mid @ Wq[l]
        sgemm_kernel<<<gemm_grid, 256>>>(midb, Wq + (size_t)l * C_DIM * C_DIM, nullptr, nullptr,
                                         qbuf, N_NODES, C_DIM, C_DIM, 0);
        mem_attn_kernel<<<(N_NODES + 7) / 8, 256>>>(qbuf, midb, nin, kbuf, vbuf, nout);
        float* tmp = nin; nin = nout; nout = tmp;
    }

    zero_float_kernel<<<1, 256>>>(pool, C_DIM);
    pool_kernel<<<148, 256>>>(nin, pool);
    final_kernel<<<1, 512>>>(pool, mem, Wc, bc, out);
}

// round 2
// speedup vs baseline: 1.6484x; 1.6484x over previous
#include <cuda_runtime.h>
#include <cstdint>

#define N_NODES 20000
#define N_EDGES 320000
#define C_DIM   256
#define H_HEADS 8
#define D_HEAD  32
#define L_LAYERS 5
#define T_DIM   64
#define MS_SLOTS 10
#define MD_DIM  128
#define NEG_SLOPE 0.2f

// ---------------- scratch buffers (static device globals; no allocs allowed) --
__device__ float g_nodeA[N_NODES * C_DIM];
__device__ float g_nodeB[N_NODES * C_DIM];
__device__ float g_xt  [N_NODES * C_DIM];
__device__ float g_h   [N_NODES * C_DIM];
__device__ float g_q   [N_NODES * C_DIM];
__device__ float g_mid [N_NODES * C_DIM];
__device__ float g_es  [N_NODES * H_HEADS];
__device__ float g_ed  [N_NODES * H_HEADS];
__device__ float g_k   [MS_SLOTS * C_DIM];
__device__ float g_v   [MS_SLOTS * C_DIM];
__device__ float g_pool[C_DIM];
__device__ int   g_cnt   [N_NODES];
__device__ int   g_rowptr[N_NODES + 1];
__device__ int   g_cursor[N_NODES];
__device__ int   g_csrc  [N_EDGES];

// ---------------- small utility kernels --------------------------------------
__global__ void zero_int_kernel(int* p, int n) {
    int i = blockIdx.x * blockDim.x + threadIdx.x;
    if (i < n) p[i] = 0;
}
__global__ void zero_float_kernel(float* p, int n) {
    int i = blockIdx.x * blockDim.x + threadIdx.x;
    if (i < n) p[i] = 0.0f;
}

// ---------------- CSR build ---------------------------------------------------
__global__ void count_kernel(const int* __restrict__ dst, int* __restrict__ cnt) {
    int e = blockIdx.x * blockDim.x + threadIdx.x;
    if (e < N_EDGES) atomicAdd(&cnt[dst[e]], 1);
}

__global__ void scan_kernel(const int* __restrict__ cnt,
                            int* __restrict__ rowptr, int* __restrict__ cursor) {
    const int PER = (N_NODES + 1023) / 1024;   // 20
    int tid = threadIdx.x;
    int s0 = tid * PER;
    int vals[PER];
    int local = 0;
#pragma unroll
    for (int k = 0; k < PER; k++) {
        int i = s0 + k;
        vals[k] = (i < N_NODES) ? cnt[i] : 0;
        local += vals[k];
    }
    int lane = tid & 31, w = tid >> 5;
    int x = local;
#pragma unroll
    for (int off = 1; off < 32; off <<= 1) {
        int t = __shfl_up_sync(0xFFFFFFFFu, x, off);
        if (lane >= off) x += t;
    }
    __shared__ int wsum[32];
    if (lane == 31) wsum[w] = x;
    __syncthreads();
    if (w == 0) {
        int y = wsum[lane];
#pragma unroll
        for (int off = 1; off < 32; off <<= 1) {
            int t = __shfl_up_sync(0xFFFFFFFFu, y, off);
            if (lane >= off) y += t;
        }
        wsum[lane] = y;
    }
    __syncthreads();
    int warpoff = (w > 0) ? wsum[w - 1] : 0;
    int excl = warpoff + x - local;
#pragma unroll
    for (int k = 0; k < PER; k++) {
        int i = s0 + k;
        if (i < N_NODES) { rowptr[i] = excl; cursor[i] = excl; }
        excl += vals[k];
    }
    if (tid == 1023) rowptr[N_NODES] = warpoff + x;
}

__global__ void scatter_kernel(const int* __restrict__ src, const int* __restrict__ dst,
                               int* __restrict__ cursor, int* __restrict__ csrc) {
    int e = blockIdx.x * blockDim.x + threadIdx.x;
    if (e < N_EDGES) {
        int pos = atomicAdd(&cursor[dst[e]], 1);
        csrc[pos] = src[e];
    }
}

// ---------------- TF32 tensor-core GEMM ---------------------------------------
// C[MxN] = A[MxK] @ B[KxN] with epilogue.
// epi: 0 = none, 1 = relu(C + bias[col]), 2 = C + R (elementwise residual)
// Block 128x128, BK=16, 8 warps of 32x64, mma.sync.m16n8k8.tf32, double-buffered.
#define TBM 128
#define TBN 128
#define TBK 16
#define SPAD 8
#define SSTRIDE (TBM + SPAD)   // 136 words

__device__ __forceinline__ uint32_t f2tf32(float x) {
    uint32_t u;
    asm("cvt.rna.tf32.f32 %0, %1;" : "=r"(u) : "f"(x));
    return u;
}

__device__ __forceinline__ void mma_tf32(float* c, const uint32_t* a, const uint32_t* b) {
    asm volatile(
        "mma.sync.aligned.m16n8k8.row.col.f32.tf32.tf32.f32 "
        "{%0,%1,%2,%3}, {%4,%5,%6,%7}, {%8,%9}, {%0,%1,%2,%3};\n"
        : "+f"(c[0]), "+f"(c[1]), "+f"(c[2]), "+f"(c[3])
        : "r"(a[0]), "r"(a[1]), "r"(a[2]), "r"(a[3]), "r"(b[0]), "r"(b[1]));
}

__global__ __launch_bounds__(256, 2)
void tgemm_kernel(const float* __restrict__ A, const float* __restrict__ B,
                  const float* __restrict__ R, const float* __restrict__ bias,
                  float* __restrict__ C, int M, int Nn, int K, int epi) {
    __shared__ uint32_t As[2][TBK][SSTRIDE];
    __shared__ uint32_t Bs[2][TBK][SSTRIDE];

    int tid = threadIdx.x;
    int lane = tid & 31;
    int wid = tid >> 5;
    int wm = wid >> 1;          // 0..3 : warp row (32 rows)
    int wn = wid & 1;           // 0..1 : warp col (64 cols)
    int tg = lane & 3;          // tid in group
    int gid = lane >> 2;        // group id

    int bm = blockIdx.y * TBM;
    int bn = blockIdx.x * TBN;

    // global load assignments
    int a_row = tid >> 1;                 // 0..127
    int a_kg  = (tid & 1) * 8;            // 0 or 8
    int b_row = tid >> 4;                 // 0..15
    int b_col = (tid & 15) * 8;           // 0..120

    float pa[8], pb[8];
    int nk = K / TBK;

    // ---- preload tile 0 ----
    {
        int gr = bm + a_row;
        if (gr < M) {
            const float4* ap = reinterpret_cast<const float4*>(&A[(size_t)gr * K + a_kg]);
            float4 v0 = ap[0], v1 = ap[1];
            pa[0] = v0.x; pa[1] = v0.y; pa[2] = v0.z; pa[3] = v0.w;
            pa[4] = v1.x; pa[5] = v1.y; pa[6] = v1.z; pa[7] = v1.w;
        } else {
#pragma unroll
            for (int j = 0; j < 8; j++) pa[j] = 0.f;
        }
        const float4* bp = reinterpret_cast<const float4*>(&B[(size_t)b_row * Nn + bn + b_col]);
        float4 w0 = bp[0], w1 = bp[1];
        pb[0] = w0.x; pb[1] = w0.y; pb[2] = w0.z; pb[3] = w0.w;
        pb[4] = w1.x; pb[5] = w1.y; pb[6] = w1.z; pb[7] = w1.w;
    }
#pragma unroll
    for (int j = 0; j < 8; j++) As[0][a_kg + j][a_row] = f2tf32(pa[j]);
    {
        uint32_t* brow = &Bs[0][b_row][b_col];
#pragma unroll
        for (int j = 0; j < 8; j++) brow[j] = f2tf32(pb[j]);
    }
    __syncthreads();

    float acc[2][8][4];
#pragma unroll
    for (int mt = 0; mt < 2; mt++)
#pragma unroll
        for (int nt = 0; nt < 8; nt++)
#pragma unroll
            for (int r = 0; r < 4; r++) acc[mt][nt][r] = 0.f;

    for (int kt = 0; kt < nk; kt++) {
        int buf = kt & 1;
        // prefetch next tile into registers
        if (kt + 1 < nk) {
            int k0 = (kt + 1) * TBK;
            int gr = bm + a_row;
            if (gr < M) {
                const float4* ap = reinterpret_cast<const float4*>(&A[(size_t)gr * K + k0 + a_kg]);
                float4 v0 = ap[0], v1 = ap[1];
                pa[0] = v0.x; pa[1] = v0.y; pa[2] = v0.z; pa[3] = v0.w;
                pa[4] = v1.x; pa[5] = v1.y; pa[6] = v1.z; pa[7] = v1.w;
            } else {
#pragma unroll
                for (int j = 0; j < 8; j++) pa[j] = 0.f;
            }
            const float4* bp = reinterpret_cast<const float4*>(&B[(size_t)(k0 + b_row) * Nn + bn + b_col]);
            float4 w0 = bp[0], w1 = bp[1];
            pb[0] = w0.x; pb[1] = w0.y; pb[2] = w0.z; pb[3] = w0.w;
            pb[4] = w1.x; pb[5] = w1.y; pb[6] = w1.z; pb[7] = w1.w;
        }

        // compute on current buffer
#pragma unroll
        for (int ks = 0; ks < TBK; ks += 8) {
            uint32_t af[2][4];
            uint32_t bf[8][2];
#pragma unroll
            for (int mt = 0; mt < 2; mt++) {
                int m0 = wm * 32 + mt * 16 + gid;
                af[mt][0] = As[buf][ks + tg][m0];
                af[mt][1] = As[buf][ks + tg][m0 + 8];
                af[mt][2] = As[buf][ks + tg + 4][m0];
                af[mt][3] = As[buf][ks + tg + 4][m0 + 8];
            }
#pragma unroll
            for (int nt = 0; nt < 8; nt++) {
                int n0 = wn * 64 + nt * 8 + gid;
                bf[nt][0] = Bs[buf][ks + tg][n0];
                bf[nt][1] = Bs[buf][ks + tg + 4][n0];
            }
#pragma unroll
            for (int mt = 0; mt < 2; mt++)
#pragma unroll
                for (int nt = 0; nt < 8; nt++)
                    mma_tf32(acc[mt][nt], af[mt], bf[nt]);
        }

        if (kt + 1 < nk) {
            int nbuf = 1 - buf;
#pragma unroll
            for (int j = 0; j < 8; j++) As[nbuf][a_kg + j][a_row] = f2tf32(pa[j]);
            uint32_t* brow = &Bs[nbuf][b_row][b_col];
#pragma unroll
            for (int j = 0; j < 8; j++) brow[j] = f2tf32(pb[j]);
            __syncthreads();
        }
    }

    // ---- epilogue ----
#pragma unroll
    for (int mt = 0; mt < 2; mt++) {
#pragma unroll
        for (int half = 0; half < 2; half++) {
            int r = bm + wm * 32 + mt * 16 + gid + half * 8;
            if (r >= M) continue;
#pragma unroll
            for (int nt = 0; nt < 8; nt++) {
                int c = bn + wn * 64 + nt * 8 + tg * 2;
                float v0 = acc[mt][nt][half * 2 + 0];
                float v1 = acc[mt][nt][half * 2 + 1];
                if (epi == 1) {
                    v0 = fmaxf(v0 + bias[c], 0.f);
                    v1 = fmaxf(v1 + bias[c + 1], 0.f);
                } else if (epi == 2) {
                    const float2 rv = *reinterpret_cast<const float2*>(&R[(size_t)r * Nn + c]);
                    v0 += rv.x; v1 += rv.y;
                }
                *reinterpret_cast<float2*>(&C[(size_t)r * Nn + c]) = make_float2(v0, v1);
            }
        }
    }
}

// ---------------- k/v projection ----------------------------------------------
__global__ void kv_kernel(const float* __restrict__ mem, const float* __restrict__ Wk,
                          const float* __restrict__ Wv,
                          float* __restrict__ kout, float* __restrict__ vout) {
    __shared__ float sm[MS_SLOTS * MD_DIM];
    int m = blockIdx.x;
    int c = threadIdx.x;
    for (int i = threadIdx.x; i < MS_SLOTS * MD_DIM; i += blockDim.x) sm[i] = mem[i];
    __syncthreads();
    float ak = 0.f, av = 0.f;
    const float* mr = &sm[m * MD_DIM];
#pragma unroll 4
    for (int t = 0; t < MD_DIM; t++) {
        float mv = mr[t];
        ak += mv * Wk[t * C_DIM + c];
        av += mv * Wv[t * C_DIM + c];
    }
    kout[m * C_DIM + c] = ak;
    vout[m * C_DIM + c] = av;
}

// ---------------- e_src / e_dst ----------------------------------------------
__global__ void attn_vec_kernel(const float* __restrict__ h, const float* __restrict__ a_s,
                                const float* __restrict__ a_d,
                                float* __restrict__ es, float* __restrict__ ed) {
    __shared__ float sa[C_DIM], sd[C_DIM];
    for (int i = threadIdx.x; i < C_DIM; i += blockDim.x) { sa[i] = a_s[i]; sd[i] = a_d[i]; }
    __syncthreads();
    int idx = blockIdx.x * blockDim.x + threadIdx.x;
    if (idx >= N_NODES * H_HEADS) return;
    int n = idx >> 3, j = idx & 7;
    const float4* hr = reinterpret_cast<const float4*>(&h[(size_t)n * C_DIM + j * D_HEAD]);
    const float4* ar = reinterpret_cast<const float4*>(&sa[j * D_HEAD]);
    const float4* dr = reinterpret_cast<const float4*>(&sd[j * D_HEAD]);
    float accs = 0.f, accd = 0.f;
#pragma unroll
    for (int k = 0; k < 8; k++) {
        float4 hv = hr[k], avv = ar[k], dv = dr[k];
        accs += hv.x * avv.x + hv.y * avv.y + hv.z * avv.z + hv.w * avv.w;
        accd += hv.x * dv.x + hv.y * dv.y + hv.z * dv.z + hv.w * dv.w;
    }
    es[idx] = accs;
    ed[idx] = accd;
}

// ---------------- edge aggregation --------------------------------------------
__global__ __launch_bounds__(256)
void edge_agg_kernel(const float* __restrict__ h, const int* __restrict__ rowptr,
                     const int* __restrict__ csrc, const float* __restrict__ es,
                     const float* __restrict__ ed, float* __restrict__ out) {
    __shared__ float sw[8][32][8];
    __shared__ int   ss[8][32];
    int warp = threadIdx.x >> 5, lane = threadIdx.x & 31;
    int n = blockIdx.x * 8 + warp;
    if (n >= N_NODES) return;
    int beg = rowptr[n], end = rowptr[n + 1];

    float edn[8];
#pragma unroll
    for (int j = 0; j < 8; j++) edn[j] = ed[n * 8 + j];

    float mh[8];
#pragma unroll
    for (int j = 0; j < 8; j++) mh[j] = -1e30f;
    for (int i = beg + lane; i < end; i += 32) {
        int s = csrc[i];
#pragma unroll
        for (int j = 0; j < 8; j++) {
            float lg = es[s * 8 + j] + edn[j];
            lg = (lg > 0.f) ? lg : NEG_SLOPE * lg;
            mh[j] = fmaxf(mh[j], lg);
        }
    }
#pragma unroll
    for (int off = 16; off > 0; off >>= 1)
#pragma unroll
        for (int j = 0; j < 8; j++) mh[j] = fmaxf(mh[j], __shfl_xor_sync(0xFFFFFFFFu, mh[j], off));

    int head = lane >> 2;
    float acc[8];
#pragma unroll
    for (int k = 0; k < 8; k++) acc[k] = 0.f;
    float dsum[8];
#pragma unroll
    for (int j = 0; j < 8; j++) dsum[j] = 0.f;

    for (int base = beg; base < end; base += 32) {
        int i = base + lane;
        int s = -1;
        float w[8];
        if (i < end) {
            s = csrc[i];
#pragma unroll
            for (int j = 0; j < 8; j++) {
                float lg = es[s * 8 + j] + edn[j];
                lg = (lg > 0.f) ? lg : NEG_SLOPE * lg;
                w[j] = __expf(lg - mh[j]);
                dsum[j] += w[j];
            }
        } else {
#pragma unroll
            for (int j = 0; j < 8; j++) w[j] = 0.f;
        }
        ss[warp][lane] = s;
#pragma unroll
        for (int j = 0; j < 8; j++) sw[warp][lane][j] = w[j];
        __syncwarp();
        int cnt = min(32, end - base);
        for (int e2 = 0; e2 < cnt; e2++) {
            int se = ss[warp][e2];
            float we = sw[warp][e2][head];
            const float4* hp = reinterpret_cast<const float4*>(&h[(size_t)se * C_DIM + lane * 8]);
            float4 h0 = hp[0], h1 = hp[1];
            acc[0] += we * h0.x; acc[1] += we * h0.y; acc[2] += we * h0.z; acc[3] += we * h0.w;
            acc[4] += we * h1.x; acc[5] += we * h1.y; acc[6] += we * h1.z; acc[7] += we * h1.w;
        }
        __syncwarp();
    }
#pragma unroll
    for (int off = 16; off > 0; off >>= 1)
#pragma unroll
        for (int j = 0; j < 8; j++) dsum[j] += __shfl_xor_sync(0xFFFFFFFFu, dsum[j], off);

    float inv = 1.0f / (dsum[head] + 1e-16f);
    float4 o0, o1;
    o0.x = fmaxf(acc[0] * inv, 0.f); o0.y = fmaxf(acc[1] * inv, 0.f);
    o0.z = fmaxf(acc[2] * inv, 0.f); o0.w = fmaxf(acc[3] * inv, 0.f);
    o1.x = fmaxf(acc[4] * inv, 0.f); o1.y = fmaxf(acc[5] * inv, 0.f);
    o1.z = fmaxf(acc[6] * inv, 0.f); o1.w = fmaxf(acc[7] * inv, 0.f);
    float4* op = reinterpret_cast<float4*>(&out[(size_t)n * C_DIM + lane * 8]);
    op[0] = o0; op[1] = o1;
}

// ---------------- memory cross-attention + residual + relu -------------------
__global__ __launch_bounds__(256)
void mem_attn_kernel(const float* __restrict__ q, const float* __restrict__ mid,
                     const float* __restrict__ xin, const float* __restrict__ kb,
                     const float* __restrict__ vb, float* __restrict__ out) {
    __shared__ float sk[MS_SLOTS][C_DIM];
    __shared__ float sv[MS_SLOTS][C_DIM];
    for (int i = threadIdx.x; i < MS_SLOTS * C_DIM; i += blockDim.x) {
        (&sk[0][0])[i] = kb[i];
        (&sv[0][0])[i] = vb[i];
    }
    __syncthreads();
    int warp = threadIdx.x >> 5, lane = threadIdx.x & 31;
    int n = blockIdx.x * 8 + warp;
    if (n >= N_NODES) return;

    const float4* qp = reinterpret_cast<const float4*>(&q[(size_t)n * C_DIM + lane * 8]);
    float4 q0 = qp[0], q1 = qp[1];
    float s[MS_SLOTS];
#pragma unroll
    for (int m = 0; m < MS_SLOTS; m++) {
        const float4* kp = reinterpret_cast<const float4*>(&sk[m][lane * 8]);
        float4 k0 = kp[0], k1 = kp[1];
        float p = q0.x * k0.x + q0.y * k0.y + q0.z * k0.z + q0.w * k0.w
                + q1.x * k1.x + q1.y * k1.y + q1.z * k1.z + q1.w * k1.w;
#pragma unroll
        for (int off = 16; off > 0; off >>= 1) p += __shfl_xor_sync(0xFFFFFFFFu, p, off);
        s[m] = p * 0.0625f;
    }
    float mx = s[0];
#pragma unroll
    for (int m = 1; m < MS_SLOTS; m++) mx = fmaxf(mx, s[m]);
    float sum = 0.f;
#pragma unroll
    for (int m = 0; m < MS_SLOTS; m++) { s[m] = __expf(s[m] - mx); sum += s[m]; }
    float invs = 1.0f / sum;

    const float4* mp = reinterpret_cast<const float4*>(&mid[(size_t)n * C_DIM + lane * 8]);
    const float4* xp = reinterpret_cast<const float4*>(&xin[(size_t)n * C_DIM + lane * 8]);
    float4 m0 = mp[0], m1 = mp[1], x0 = xp[0], x1 = xp[1];
    float acc[8] = {m0.x + x0.x, m0.y + x0.y, m0.z + x0.z, m0.w + x0.w,
                    m1.x + x1.x, m1.y + x1.y, m1.z + x1.z, m1.w + x1.w};
#pragma unroll
    for (int m = 0; m < MS_SLOTS; m++) {
        float a = s[m] * invs;
        const float4* vp = reinterpret_cast<const float4*>(&sv[m][lane * 8]);
        float4 v0 = vp[0], v1 = vp[1];
        acc[0] += a * v0.x; acc[1] += a * v0.y; acc[2] += a * v0.z; acc[3] += a * v0.w;
        acc[4] += a * v1.x; acc[5] += a * v1.y; acc[6] += a * v1.z; acc[7] += a * v1.w;
    }
    float4 o0 = make_float4(fmaxf(acc[0], 0.f), fmaxf(acc[1], 0.f), fmaxf(acc[2], 0.f), fmaxf(acc[3], 0.f));
    float4 o1 = make_float4(fmaxf(acc[4], 0.f), fmaxf(acc[5], 0.f), fmaxf(acc[6], 0.f), fmaxf(acc[7], 0.f));
    float4* op = reinterpret_cast<float4*>(&out[(size_t)n * C_DIM + lane * 8]);
    op[0] = o0; op[1] = o1;
}

// ---------------- pooling + final projection ----------------------------------
__global__ void pool_kernel(const float* __restrict__ node, float* __restrict__ pool) {
    int c = threadIdx.x;
    float acc = 0.f;
    for (int r = blockIdx.x; r < N_NODES; r += gridDim.x) acc += node[(size_t)r * C_DIM + c];
    atomicAdd(&pool[c], acc);
}

__global__ void final_kernel(const float* __restrict__ pool, const float* __restrict__ mem,
                             const float* __restrict__ Wc, const float* __restrict__ bc,
                             float* __restrict__ out) {
    __shared__ float s0[512], s1[512];
    int i = threadIdx.x;
    float val = 0.f;
    if (i < C_DIM) {
        val = pool[i] * (1.0f / (float)N_NODES);
    } else if (i < C_DIM + MD_DIM) {
        int t = i - C_DIM;
        float a = 0.f;
#pragma unroll
        for (int m = 0; m < MS_SLOTS; m++) a += mem[m * MD_DIM + t];
        val = a * (1.0f / (float)MS_SLOTS);
    }
    float c0 = 0.f, c1 = 0.f;
    if (i < C_DIM + MD_DIM) { c0 = val * Wc[i * 2 + 0]; c1 = val * Wc[i * 2 + 1]; }
    s0[i] = c0; s1[i] = c1;
    __syncthreads();
    for (int st = 256; st > 0; st >>= 1) {
        if (i < st) { s0[i] += s0[i + st]; s1[i] += s1[i + st]; }
        __syncthreads();
    }
    if (i == 0) { out[0] = s0[0] + bc[0]; out[1] = s1[0] + bc[1]; }
}

// ---------------- host launch -------------------------------------------------
static void* getsym(const void* symbol) {
    void* p = nullptr;
    cudaGetSymbolAddress(&p, symbol);
    return p;
}

extern "C" void kernel_launch(void* const* d_in, const int* in_sizes, int n_in,
                              void* d_out, int out_size) {
    const float* x    = (const float*)d_in[0];
    const int*   ei   = (const int*)  d_in[1];
    const float* te   = (const float*)d_in[2];
    const float* Wi   = (const float*)d_in[3];
    const float* bi   = (const float*)d_in[4];
    const float* Wg   = (const float*)d_in[5];
    const float* a_s  = (const float*)d_in[6];
    const float* a_d  = (const float*)d_in[7];
    const float* Wt   = (const float*)d_in[8];
    const float* Wq   = (const float*)d_in[9];
    const float* Wk   = (const float*)d_in[10];
    const float* Wv   = (const float*)d_in[11];
    const float* mem  = (const float*)d_in[12];
    const float* Wc   = (const float*)d_in[13];
    const float* bc   = (const float*)d_in[14];
    float* out = (float*)d_out;

    float* nodeA = (float*)getsym(g_nodeA);
    float* nodeB = (float*)getsym(g_nodeB);
    float* xt    = (float*)getsym(g_xt);
    float* hbuf  = (float*)getsym(g_h);
    float* qbuf  = (float*)getsym(g_q);
    float* midb  = (float*)getsym(g_mid);
    float* esb   = (float*)getsym(g_es);
    float* edb   = (float*)getsym(g_ed);
    float* kbuf  = (float*)getsym(g_k);
    float* vbuf  = (float*)getsym(g_v);
    float* pool  = (float*)getsym(g_pool);
    int* cnt     = (int*)getsym(g_cnt);
    int* rowptr  = (int*)getsym(g_rowptr);
    int* cursor  = (int*)getsym(g_cursor);
    int* csrc    = (int*)getsym(g_csrc);

    const int* src = ei;
    const int* dst = ei + N_EDGES;

    // CSR build
    zero_int_kernel<<<(N_NODES + 255) / 256, 256>>>(cnt, N_NODES);
    count_kernel<<<(N_EDGES + 255) / 256, 256>>>(dst, cnt);
    scan_kernel<<<1, 1024>>>(cnt, rowptr, cursor);
    scatter_kernel<<<(N_EDGES + 255) / 256, 256>>>(src, dst, cursor, csrc);

    dim3 gemm_grid(C_DIM / TBN, (N_NODES + TBM - 1) / TBM);

    // input projection: nodeA = relu(x @ Wi + bi)
    tgemm_kernel<<<gemm_grid, 256>>>(x, Wi, nullptr, bi, nodeA, N_NODES, C_DIM, 128, 1);

    float* nin = nodeA;
    float* nout = nodeB;
    for (int l = 0; l < L_LAYERS; l++) {
        kv_kernel<<<MS_SLOTS, 256>>>(mem, Wk + (size_t)l * MD_DIM * C_DIM,
                                     Wv + (size_t)l * MD_DIM * C_DIM, kbuf, vbuf);
        // xt = nin + te @ Wt[l]
        tgemm_kernel<<<gemm_grid, 256>>>(te, Wt + (size_t)l * T_DIM * C_DIM, nin, nullptr,
                                         xt, N_NODES, C_DIM, T_DIM, 2);
        // h = xt @ Wg[l]
        tgemm_kernel<<<gemm_grid, 256>>>(xt, Wg + (size_t)l * C_DIM * C_DIM, nullptr, nullptr,
                                         hbuf, N_NODES, C_DIM, C_DIM, 0);
        attn_vec_kernel<<<(N_NODES * H_HEADS + 255) / 256, 256>>>(
            hbuf, a_s + l * H_HEADS * D_HEAD, a_d + l * H_HEADS * D_HEAD, esb, edb);
        edge_agg_kernel<<<(N_NODES + 7) / 8, 256>>>(hbuf, rowptr, csrc, esb, edb, midb);
        // q = mid @ Wq[l]
        tgemm_kernel<<<gemm_grid, 256>>>(midb, Wq + (size_t)l * C_DIM * C_DIM, nullptr, nullptr,
                                         qbuf, N_NODES, C_DIM, C_DIM, 0);
        mem_attn_kernel<<<(N_NODES + 7) / 8, 256>>>(qbuf, midb, nin, kbuf, vbuf, nout);
        float* tmp = nin; nin = nout; nout = tmp;
    }

    zero_float_kernel<<<1, 256>>>(pool, C_DIM);
    pool_kernel<<<148, 256>>>(nin, pool);
    final_kernel<<<1, 512>>>(pool, mem, Wc, bc, out);
}

// round 3
// speedup vs baseline: 1.7755x; 1.0771x over previous
#include <cuda_runtime.h>
#include <cstdint>

#define N_NODES 20000
#define N_EDGES 320000
#define C_DIM   256
#define H_HEADS 8
#define D_HEAD  32
#define L_LAYERS 5
#define T_DIM   64
#define MS_SLOTS 10
#define MD_DIM  128
#define NEG_SLOPE 0.2f

// ---------------- scratch buffers (static device globals; no allocs allowed) --
__device__ float g_nodeA[N_NODES * C_DIM];
__device__ float g_nodeB[N_NODES * C_DIM];
__device__ float g_xt  [N_NODES * C_DIM];
__device__ float g_h   [N_NODES * C_DIM];
__device__ float g_q   [N_NODES * C_DIM];
__device__ float g_mid [N_NODES * C_DIM];
__device__ float g_es  [N_NODES * H_HEADS];
__device__ float g_ed  [N_NODES * H_HEADS];
__device__ float g_k   [MS_SLOTS * C_DIM];
__device__ float g_v   [MS_SLOTS * C_DIM];
__device__ float g_pool[C_DIM];
__device__ int   g_cnt   [N_NODES];
__device__ int   g_rowptr[N_NODES + 1];
__device__ int   g_cursor[N_NODES];
__device__ int   g_csrc  [N_EDGES];

// ---------------- small utility kernels --------------------------------------
__global__ void zero_int_kernel(int* p, int n) {
    int i = blockIdx.x * blockDim.x + threadIdx.x;
    if (i < n) p[i] = 0;
}
__global__ void zero_float_kernel(float* p, int n) {
    int i = blockIdx.x * blockDim.x + threadIdx.x;
    if (i < n) p[i] = 0.0f;
}

// ---------------- CSR build ---------------------------------------------------
__global__ void count_kernel(const int* __restrict__ dst, int* __restrict__ cnt) {
    int e = blockIdx.x * blockDim.x + threadIdx.x;
    if (e < N_EDGES) atomicAdd(&cnt[dst[e]], 1);
}

__global__ void scan_kernel(const int* __restrict__ cnt,
                            int* __restrict__ rowptr, int* __restrict__ cursor) {
    const int PER = (N_NODES + 1023) / 1024;   // 20
    int tid = threadIdx.x;
    int s0 = tid * PER;
    int vals[PER];
    int local = 0;
#pragma unroll
    for (int k = 0; k < PER; k++) {
        int i = s0 + k;
        vals[k] = (i < N_NODES) ? cnt[i] : 0;
        local += vals[k];
    }
    int lane = tid & 31, w = tid >> 5;
    int x = local;
#pragma unroll
    for (int off = 1; off < 32; off <<= 1) {
        int t = __shfl_up_sync(0xFFFFFFFFu, x, off);
        if (lane >= off) x += t;
    }
    __shared__ int wsum[32];
    if (lane == 31) wsum[w] = x;
    __syncthreads();
    if (w == 0) {
        int y = wsum[lane];
#pragma unroll
        for (int off = 1; off < 32; off <<= 1) {
            int t = __shfl_up_sync(0xFFFFFFFFu, y, off);
            if (lane >= off) y += t;
        }
        wsum[lane] = y;
    }
    __syncthreads();
    int warpoff = (w > 0) ? wsum[w - 1] : 0;
    int excl = warpoff + x - local;
#pragma unroll
    for (int k = 0; k < PER; k++) {
        int i = s0 + k;
        if (i < N_NODES) { rowptr[i] = excl; cursor[i] = excl; }
        excl += vals[k];
    }
    if (tid == 1023) rowptr[N_NODES] = warpoff + x;
}

__global__ void scatter_kernel(const int* __restrict__ src, const int* __restrict__ dst,
                               int* __restrict__ cursor, int* __restrict__ csrc) {
    int e = blockIdx.x * blockDim.x + threadIdx.x;
    if (e < N_EDGES) {
        int pos = atomicAdd(&cursor[dst[e]], 1);
        csrc[pos] = src[e];
    }
}

// ---------------- TF32 tensor-core GEMM, cp.async 3-stage ---------------------
// C[MxN] = A[MxK] @ B[KxN] with epilogue.
// epi: 0 = none, 1 = relu(C + bias[col]), 2 = C + R (elementwise residual)
// Block 160x128, TBK=16, 8 warps (2x4), warp tile 80x32, mma.sync.m16n8k8.tf32.
// REQUIRES: M % 160 == 0, N % 128 == 0, K % 16 == 0.
#define TBM 160
#define TBN 128
#define TBK 16
#define NSTAGE 3
#define ASTRIDE 20            // 16 + 4 pad (floats)
#define BSTRIDE 136           // 128 + 8 pad (floats)
#define A_STAGE (TBM * ASTRIDE)   // 3200 floats
#define B_STAGE (TBK * BSTRIDE)   // 2176 floats
#define SMEM_FLOATS (NSTAGE * (A_STAGE + B_STAGE))   // 16128 floats = 64512 B

__device__ __forceinline__ uint32_t f2tf32(float x) {
    uint32_t u;
    asm("cvt.rna.tf32.f32 %0, %1;" : "=r"(u) : "f"(x));
    return u;
}

__device__ __forceinline__ void mma_tf32(float* c, const uint32_t* a, const uint32_t* b) {
    asm volatile(
        "mma.sync.aligned.m16n8k8.row.col.f32.tf32.tf32.f32 "
        "{%0,%1,%2,%3}, {%4,%5,%6,%7}, {%8,%9}, {%0,%1,%2,%3};\n"
        : "+f"(c[0]), "+f"(c[1]), "+f"(c[2]), "+f"(c[3])
        : "r"(a[0]), "r"(a[1]), "r"(a[2]), "r"(a[3]), "r"(b[0]), "r"(b[1]));
}

__device__ __forceinline__ void cp_async16(float* dst_smem, const float* src) {
    uint32_t d = (uint32_t)__cvta_generic_to_shared(dst_smem);
    asm volatile("cp.async.cg.shared.global [%0], [%1], 16;\n" :: "r"(d), "l"(src));
}
__device__ __forceinline__ void cp_commit() {
    asm volatile("cp.async.commit_group;\n");
}
template <int NN>
__device__ __forceinline__ void cp_wait() {
    asm volatile("cp.async.wait_group %0;\n" :: "n"(NN));
}

__global__ __launch_bounds__(256, 2)
void tgemm_kernel(const float* __restrict__ A, const float* __restrict__ B,
                  const float* __restrict__ R, const float* __restrict__ bias,
                  float* __restrict__ C, int M, int Nn, int K, int epi) {
    extern __shared__ float smem[];
    float* As = smem;                       // [NSTAGE][TBM][ASTRIDE]
    float* Bs = smem + NSTAGE * A_STAGE;    // [NSTAGE][TBK][BSTRIDE]

    int tid = threadIdx.x;
    int lane = tid & 31;
    int wid = tid >> 5;
    int wm = wid >> 2;          // 0..1 : warp row (80 rows)
    int wn = wid & 3;           // 0..3 : warp col (32 cols)
    int tg = lane & 3;
    int gid = lane >> 2;

    int bm = blockIdx.y * TBM;
    int bn = blockIdx.x * TBN;
    int nk = K / TBK;

    // load assignments
    int b_r = tid >> 4;              // 0..15
    int b_c = (tid & 15) * 8;        // 0..120
    const float* a_src_base = A + (size_t)(bm + tid) * K;       // valid if tid<160
    const float* b_src_base = B + (size_t)b_r * Nn + bn + b_c;

    // prologue: issue stages 0,1
#pragma unroll
    for (int s = 0; s < 2; s++) {
        int k0 = s * TBK;
        if (s < nk) {
            if (tid < TBM) {
                float* ad = As + s * A_STAGE + tid * ASTRIDE;
                const float* asrc = a_src_base + k0;
#pragma unroll
                for (int j = 0; j < 4; j++) cp_async16(ad + j * 4, asrc + j * 4);
            }
            float* bd = Bs + s * B_STAGE + b_r * BSTRIDE + b_c;
            const float* bsrc = b_src_base + (size_t)k0 * Nn;
            cp_async16(bd, bsrc);
            cp_async16(bd + 4, bsrc + 4);
        }
        cp_commit();
    }

    float acc[5][4][4];
#pragma unroll
    for (int mt = 0; mt < 5; mt++)
#pragma unroll
        for (int nt = 0; nt < 4; nt++)
#pragma unroll
            for (int r = 0; r < 4; r++) acc[mt][nt][r] = 0.f;

    for (int kt = 0; kt < nk; kt++) {
        cp_wait<1>();
        __syncthreads();

        const float* as = As + (kt % 3) * A_STAGE;
        const float* bs = Bs + (kt % 3) * B_STAGE;

#pragma unroll
        for (int ks = 0; ks < TBK; ks += 8) {
            uint32_t bf[4][2];
#pragma unroll
            for (int nt = 0; nt < 4; nt++) {
                int n0 = wn * 32 + nt * 8 + gid;
                bf[nt][0] = f2tf32(bs[(ks + tg) * BSTRIDE + n0]);
                bf[nt][1] = f2tf32(bs[(ks + tg + 4) * BSTRIDE + n0]);
            }
#pragma unroll
            for (int mt = 0; mt < 5; mt++) {
                int m0 = wm * 80 + mt * 16 + gid;
                uint32_t af[4];
                af[0] = f2tf32(as[m0 * ASTRIDE + ks + tg]);
                af[1] = f2tf32(as[(m0 + 8) * ASTRIDE + ks + tg]);
                af[2] = f2tf32(as[m0 * ASTRIDE + ks + tg + 4]);
                af[3] = f2tf32(as[(m0 + 8) * ASTRIDE + ks + tg + 4]);
#pragma unroll
                for (int nt = 0; nt < 4; nt++)
                    mma_tf32(acc[mt][nt], af, bf[nt]);
            }
        }

        // issue stage kt+2
        int s = (kt + 2) % 3;
        if (kt + 2 < nk) {
            int k0 = (kt + 2) * TBK;
            if (tid < TBM) {
                float* ad = As + s * A_STAGE + tid * ASTRIDE;
                const float* asrc = a_src_base + k0;
#pragma unroll
                for (int j = 0; j < 4; j++) cp_async16(ad + j * 4, asrc + j * 4);
            }
            float* bd = Bs + s * B_STAGE + b_r * BSTRIDE + b_c;
            const float* bsrc = b_src_base + (size_t)k0 * Nn;
            cp_async16(bd, bsrc);
            cp_async16(bd + 4, bsrc + 4);
        }
        cp_commit();
    }

    // ---- epilogue ----
#pragma unroll
    for (int mt = 0; mt < 5; mt++) {
#pragma unroll
        for (int half = 0; half < 2; half++) {
            int r = bm + wm * 80 + mt * 16 + gid + half * 8;
#pragma unroll
            for (int nt = 0; nt < 4; nt++) {
                int c = bn + wn * 32 + nt * 8 + tg * 2;
                float v0 = acc[mt][nt][half * 2 + 0];
                float v1 = acc[mt][nt][half * 2 + 1];
                if (epi == 1) {
                    v0 = fmaxf(v0 + bias[c], 0.f);
                    v1 = fmaxf(v1 + bias[c + 1], 0.f);
                } else if (epi == 2) {
                    const float2 rv = *reinterpret_cast<const float2*>(&R[(size_t)r * Nn + c]);
                    v0 += rv.x; v1 += rv.y;
                }
                *reinterpret_cast<float2*>(&C[(size_t)r * Nn + c]) = make_float2(v0, v1);
            }
        }
    }
}

// ---------------- k/v projection ----------------------------------------------
__global__ void kv_kernel(const float* __restrict__ mem, const float* __restrict__ Wk,
                          const float* __restrict__ Wv,
                          float* __restrict__ kout, float* __restrict__ vout) {
    __shared__ float sm[MS_SLOTS * MD_DIM];
    int m = blockIdx.x;
    int c = threadIdx.x;
    for (int i = threadIdx.x; i < MS_SLOTS * MD_DIM; i += blockDim.x) sm[i] = mem[i];
    __syncthreads();
    float ak = 0.f, av = 0.f;
    const float* mr = &sm[m * MD_DIM];
#pragma unroll 4
    for (int t = 0; t < MD_DIM; t++) {
        float mv = mr[t];
        ak += mv * Wk[t * C_DIM + c];
        av += mv * Wv[t * C_DIM + c];
    }
    kout[m * C_DIM + c] = ak;
    vout[m * C_DIM + c] = av;
}

// ---------------- e_src / e_dst ----------------------------------------------
__global__ void attn_vec_kernel(const float* __restrict__ h, const float* __restrict__ a_s,
                                const float* __restrict__ a_d,
                                float* __restrict__ es, float* __restrict__ ed) {
    __shared__ float sa[C_DIM], sd[C_DIM];
    for (int i = threadIdx.x; i < C_DIM; i += blockDim.x) { sa[i] = a_s[i]; sd[i] = a_d[i]; }
    __syncthreads();
    int idx = blockIdx.x * blockDim.x + threadIdx.x;
    if (idx >= N_NODES * H_HEADS) return;
    int n = idx >> 3, j = idx & 7;
    const float4* hr = reinterpret_cast<const float4*>(&h[(size_t)n * C_DIM + j * D_HEAD]);
    const float4* ar = reinterpret_cast<const float4*>(&sa[j * D_HEAD]);
    const float4* dr = reinterpret_cast<const float4*>(&sd[j * D_HEAD]);
    float accs = 0.f, accd = 0.f;
#pragma unroll
    for (int k = 0; k < 8; k++) {
        float4 hv = hr[k], avv = ar[k], dv = dr[k];
        accs += hv.x * avv.x + hv.y * avv.y + hv.z * avv.z + hv.w * avv.w;
        accd += hv.x * dv.x + hv.y * dv.y + hv.z * dv.z + hv.w * dv.w;
    }
    es[idx] = accs;
    ed[idx] = accd;
}

// ---------------- edge aggregation --------------------------------------------
__global__ __launch_bounds__(256)
void edge_agg_kernel(const float* __restrict__ h, const int* __restrict__ rowptr,
                     const int* __restrict__ csrc, const float* __restrict__ es,
                     const float* __restrict__ ed, float* __restrict__ out) {
    __shared__ float sw[8][32][8];
    __shared__ int   ss[8][32];
    int warp = threadIdx.x >> 5, lane = threadIdx.x & 31;
    int n = blockIdx.x * 8 + warp;
    if (n >= N_NODES) return;
    int beg = rowptr[n], end = rowptr[n + 1];

    float edn[8];
#pragma unroll
    for (int j = 0; j < 8; j++) edn[j] = ed[n * 8 + j];

    float mh[8];
#pragma unroll
    for (int j = 0; j < 8; j++) mh[j] = -1e30f;
    for (int i = beg + lane; i < end; i += 32) {
        int s = csrc[i];
#pragma unroll
        for (int j = 0; j < 8; j++) {
            float lg = es[s * 8 + j] + edn[j];
            lg = (lg > 0.f) ? lg : NEG_SLOPE * lg;
            mh[j] = fmaxf(mh[j], lg);
        }
    }
#pragma unroll
    for (int off = 16; off > 0; off >>= 1)
#pragma unroll
        for (int j = 0; j < 8; j++) mh[j] = fmaxf(mh[j], __shfl_xor_sync(0xFFFFFFFFu, mh[j], off));

    int head = lane >> 2;
    float acc[8];
#pragma unroll
    for (int k = 0; k < 8; k++) acc[k] = 0.f;
    float dsum[8];
#pragma unroll
    for (int j = 0; j < 8; j++) dsum[j] = 0.f;

    for (int base = beg; base < end; base += 32) {
        int i = base + lane;
        int s = -1;
        float w[8];
        if (i < end) {
            s = csrc[i];
#pragma unroll
            for (int j = 0; j < 8; j++) {
                float lg = es[s * 8 + j] + edn[j];
                lg = (lg > 0.f) ? lg : NEG_SLOPE * lg;
                w[j] = __expf(lg - mh[j]);
                dsum[j] += w[j];
            }
        } else {
#pragma unroll
            for (int j = 0; j < 8; j++) w[j] = 0.f;
        }
        ss[warp][lane] = s;
#pragma unroll
        for (int j = 0; j < 8; j++) sw[warp][lane][j] = w[j];
        __syncwarp();
        int cnt = min(32, end - base);
        for (int e2 = 0; e2 < cnt; e2++) {
            int se = ss[warp][e2];
            float we = sw[warp][e2][head];
            const float4* hp = reinterpret_cast<const float4*>(&h[(size_t)se * C_DIM + lane * 8]);
            float4 h0 = hp[0], h1 = hp[1];
            acc[0] += we * h0.x; acc[1] += we * h0.y; acc[2] += we * h0.z; acc[3] += we * h0.w;
            acc[4] += we * h1.x; acc[5] += we * h1.y; acc[6] += we * h1.z; acc[7] += we * h1.w;
        }
        __syncwarp();
    }
#pragma unroll
    for (int off = 16; off > 0; off >>= 1)
#pragma unroll
        for (int j = 0; j < 8; j++) dsum[j] += __shfl_xor_sync(0xFFFFFFFFu, dsum[j], off);

    float inv = 1.0f / (dsum[head] + 1e-16f);
    float4 o0, o1;
    o0.x = fmaxf(acc[0] * inv, 0.f); o0.y = fmaxf(acc[1] * inv, 0.f);
    o0.z = fmaxf(acc[2] * inv, 0.f); o0.w = fmaxf(acc[3] * inv, 0.f);
    o1.x = fmaxf(acc[4] * inv, 0.f); o1.y = fmaxf(acc[5] * inv, 0.f);
    o1.z = fmaxf(acc[6] * inv, 0.f); o1.w = fmaxf(acc[7] * inv, 0.f);
    float4* op = reinterpret_cast<float4*>(&out[(size_t)n * C_DIM + lane * 8]);
    op[0] = o0; op[1] = o1;
}

// ---------------- memory cross-attention + residual + relu -------------------
__global__ __launch_bounds__(256)
void mem_attn_kernel(const float* __restrict__ q, const float* __restrict__ mid,
                     const float* __restrict__ xin, const float* __restrict__ kb,
                     const float* __restrict__ vb, float* __restrict__ out) {
    __shared__ float sk[MS_SLOTS][C_DIM];
    __shared__ float sv[MS_SLOTS][C_DIM];
    for (int i = threadIdx.x; i < MS_SLOTS * C_DIM; i += blockDim.x) {
        (&sk[0][0])[i] = kb[i];
        (&sv[0][0])[i] = vb[i];
    }
    __syncthreads();
    int warp = threadIdx.x >> 5, lane = threadIdx.x & 31;
    int n = blockIdx.x * 8 + warp;
    if (n >= N_NODES) return;

    const float4* qp = reinterpret_cast<const float4*>(&q[(size_t)n * C_DIM + lane * 8]);
    float4 q0 = qp[0], q1 = qp[1];
    float s[MS_SLOTS];
#pragma unroll
    for (int m = 0; m < MS_SLOTS; m++) {
        const float4* kp = reinterpret_cast<const float4*>(&sk[m][lane * 8]);
        float4 k0 = kp[0], k1 = kp[1];
        float p = q0.x * k0.x + q0.y * k0.y + q0.z * k0.z + q0.w * k0.w
                + q1.x * k1.x + q1.y * k1.y + q1.z * k1.z + q1.w * k1.w;
#pragma unroll
        for (int off = 16; off > 0; off >>= 1) p += __shfl_xor_sync(0xFFFFFFFFu, p, off);
        s[m] = p * 0.0625f;
    }
    float mx = s[0];
#pragma unroll
    for (int m = 1; m < MS_SLOTS; m++) mx = fmaxf(mx, s[m]);
    float sum = 0.f;
#pragma unroll
    for (int m = 0; m < MS_SLOTS; m++) { s[m] = __expf(s[m] - mx); sum += s[m]; }
    float invs = 1.0f / sum;

    const float4* mp = reinterpret_cast<const float4*>(&mid[(size_t)n * C_DIM + lane * 8]);
    const float4* xp = reinterpret_cast<const float4*>(&xin[(size_t)n * C_DIM + lane * 8]);
    float4 m0 = mp[0], m1 = mp[1], x0 = xp[0], x1 = xp[1];
    float acc[8] = {m0.x + x0.x, m0.y + x0.y, m0.z + x0.z, m0.w + x0.w,
                    m1.x + x1.x, m1.y + x1.y, m1.z + x1.z, m1.w + x1.w};
#pragma unroll
    for (int m = 0; m < MS_SLOTS; m++) {
        float a = s[m] * invs;
        const float4* vp = reinterpret_cast<const float4*>(&sv[m][lane * 8]);
        float4 v0 = vp[0], v1 = vp[1];
        acc[0] += a * v0.x; acc[1] += a * v0.y; acc[2] += a * v0.z; acc[3] += a * v0.w;
        acc[4] += a * v1.x; acc[5] += a * v1.y; acc[6] += a * v1.z; acc[7] += a * v1.w;
    }
    float4 o0 = make_float4(fmaxf(acc[0], 0.f), fmaxf(acc[1], 0.f), fmaxf(acc[2], 0.f), fmaxf(acc[3], 0.f));
    float4 o1 = make_float4(fmaxf(acc[4], 0.f), fmaxf(acc[5], 0.f), fmaxf(acc[6], 0.f), fmaxf(acc[7], 0.f));
    float4* op = reinterpret_cast<float4*>(&out[(size_t)n * C_DIM + lane * 8]);
    op[0] = o0; op[1] = o1;
}

// ---------------- pooling + final projection ----------------------------------
__global__ void pool_kernel(const float* __restrict__ node, float* __restrict__ pool) {
    int c = threadIdx.x;
    float acc = 0.f;
    for (int r = blockIdx.x; r < N_NODES; r += gridDim.x) acc += node[(size_t)r * C_DIM + c];
    atomicAdd(&pool[c], acc);
}

__global__ void final_kernel(const float* __restrict__ pool, const float* __restrict__ mem,
                             const float* __restrict__ Wc, const float* __restrict__ bc,
                             float* __restrict__ out) {
    __shared__ float s0[512], s1[512];
    int i = threadIdx.x;
    float val = 0.f;
    if (i < C_DIM) {
        val = pool[i] * (1.0f / (float)N_NODES);
    } else if (i < C_DIM + MD_DIM) {
        int t = i - C_DIM;
        float a = 0.f;
#pragma unroll
        for (int m = 0; m < MS_SLOTS; m++) a += mem[m * MD_DIM + t];
        val = a * (1.0f / (float)MS_SLOTS);
    }
    float c0 = 0.f, c1 = 0.f;
    if (i < C_DIM + MD_DIM) { c0 = val * Wc[i * 2 + 0]; c1 = val * Wc[i * 2 + 1]; }
    s0[i] = c0; s1[i] = c1;
    __syncthreads();
    for (int st = 256; st > 0; st >>= 1) {
        if (i < st) { s0[i] += s0[i + st]; s1[i] += s1[i + st]; }
        __syncthreads();
    }
    if (i == 0) { out[0] = s0[0] + bc[0]; out[1] = s1[0] + bc[1]; }
}

// ---------------- host launch -------------------------------------------------
static void* getsym(const void* symbol) {
    void* p = nullptr;
    cudaGetSymbolAddress(&p, symbol);
    return p;
}

extern "C" void kernel_launch(void* const* d_in, const int* in_sizes, int n_in,
                              void* d_out, int out_size) {
    const float* x    = (const float*)d_in[0];
    const int*   ei   = (const int*)  d_in[1];
    const float* te   = (const float*)d_in[2];
    const float* Wi   = (const float*)d_in[3];
    const float* bi   = (const float*)d_in[4];
    const float* Wg   = (const float*)d_in[5];
    const float* a_s  = (const float*)d_in[6];
    const float* a_d  = (const float*)d_in[7];
    const float* Wt   = (const float*)d_in[8];
    const float* Wq   = (const float*)d_in[9];
    const float* Wk   = (const float*)d_in[10];
    const float* Wv   = (const float*)d_in[11];
    const float* mem  = (const float*)d_in[12];
    const float* Wc   = (const float*)d_in[13];
    const float* bc   = (const float*)d_in[14];
    float* out = (float*)d_out;

    float* nodeA = (float*)getsym(g_nodeA);
    float* nodeB = (float*)getsym(g_nodeB);
    float* xt    = (float*)getsym(g_xt);
    float* hbuf  = (float*)getsym(g_h);
    float* qbuf  = (float*)getsym(g_q);
    float* midb  = (float*)getsym(g_mid);
    float* esb   = (float*)getsym(g_es);
    float* edb   = (float*)getsym(g_ed);
    float* kbuf  = (float*)getsym(g_k);
    float* vbuf  = (float*)getsym(g_v);
    float* pool  = (float*)getsym(g_pool);
    int* cnt     = (int*)getsym(g_cnt);
    int* rowptr  = (int*)getsym(g_rowptr);
    int* cursor  = (int*)getsym(g_cursor);
    int* csrc    = (int*)getsym(g_csrc);

    const int* src = ei;
    const int* dst = ei + N_EDGES;

    const int smem_bytes = SMEM_FLOATS * 4;   // 64512
    static bool attr_set = false;
    if (!attr_set) {
        cudaFuncSetAttribute(tgemm_kernel, cudaFuncAttributeMaxDynamicSharedMemorySize, smem_bytes);
        attr_set = true;
    }

    // CSR build
    zero_int_kernel<<<(N_NODES + 255) / 256, 256>>>(cnt, N_NODES);
    count_kernel<<<(N_EDGES + 255) / 256, 256>>>(dst, cnt);
    scan_kernel<<<1, 1024>>>(cnt, rowptr, cursor);
    scatter_kernel<<<(N_EDGES + 255) / 256, 256>>>(src, dst, cursor, csrc);

    dim3 gemm_grid(C_DIM / TBN, N_NODES / TBM);   // (2, 125)

    // input projection: nodeA = relu(x @ Wi + bi)
    tgemm_kernel<<<gemm_grid, 256, smem_bytes>>>(x, Wi, nullptr, bi, nodeA, N_NODES, C_DIM, 128, 1);

    float* nin = nodeA;
    float* nout = nodeB;
    for (int l = 0; l < L_LAYERS; l++) {
        kv_kernel<<<MS_SLOTS, 256>>>(mem, Wk + (size_t)l * MD_DIM * C_DIM,
                                     Wv + (size_t)l * MD_DIM * C_DIM, kbuf, vbuf);
        // xt = nin + te @ Wt[l]
        tgemm_kernel<<<gemm_grid, 256, smem_bytes>>>(te, Wt + (size_t)l * T_DIM * C_DIM, nin, nullptr,
                                                     xt, N_NODES, C_DIM, T_DIM, 2);
        // h = xt @ Wg[l]
        tgemm_kernel<<<gemm_grid, 256, smem_bytes>>>(xt, Wg + (size_t)l * C_DIM * C_DIM, nullptr, nullptr,
                                                     hbuf, N_NODES, C_DIM, C_DIM, 0);
        attn_vec_kernel<<<(N_NODES * H_HEADS + 255) / 256, 256>>>(
            hbuf, a_s + l * H_HEADS * D_HEAD, a_d + l * H_HEADS * D_HEAD, esb, edb);
        edge_agg_kernel<<<(N_NODES + 7) / 8, 256>>>(hbuf, rowptr, csrc, esb, edb, midb);
        // q = mid @ Wq[l]
        tgemm_kernel<<<gemm_grid, 256, smem_bytes>>>(midb, Wq + (size_t)l * C_DIM * C_DIM, nullptr, nullptr,
                                                     qbuf, N_NODES, C_DIM, C_DIM, 0);
        mem_attn_kernel<<<(N_NODES + 7) / 8, 256>>>(qbuf, midb, nin, kbuf, vbuf, nout);
        float* tmp = nin; nin = nout; nout = tmp;
    }

    zero_float_kernel<<<1, 256>>>(pool, C_DIM);
    pool_kernel<<<148, 256>>>(nin, pool);
    final_kernel<<<1, 512>>>(pool, mem, Wc, bc, out);
}

// round 4
// speedup vs baseline: 2.4000x; 1.3517x over previous
#include <cuda_runtime.h>
#include <cstdint>

#define N_NODES 20000
#define N_EDGES 320000
#define C_DIM   256
#define H_HEADS 8
#define D_HEAD  32
#define L_LAYERS 5
#define T_DIM   64
#define MS_SLOTS 10
#define MD_DIM  128
#define NEG_SLOPE 0.2f
#define TP_LD   (L_LAYERS * C_DIM)   // 1280

// ---------------- scratch buffers (static device globals; no allocs allowed) --
__device__ float g_nodeA[N_NODES * C_DIM];
__device__ float g_nodeB[N_NODES * C_DIM];
__device__ float g_xt  [N_NODES * C_DIM];
__device__ float g_h   [N_NODES * C_DIM];
__device__ float g_mid [N_NODES * C_DIM];
__device__ float g_tpall[N_NODES * TP_LD];          // all-layer t_proj
__device__ float g_Wtall[T_DIM * TP_LD];            // reshaped Wt
__device__ float g_es  [N_NODES * H_HEADS];
__device__ float g_ed  [N_NODES * H_HEADS];
__device__ float g_kall [L_LAYERS * MS_SLOTS * C_DIM];
__device__ float g_vall [L_LAYERS * MS_SLOTS * C_DIM];
__device__ float g_Ptall[L_LAYERS * MS_SLOTS * C_DIM];  // Pt[l][m][c] = (Wq_l @ k_l^T)[c][m]
__device__ float g_pool[C_DIM];
__device__ int   g_cnt   [N_NODES];
__device__ int   g_rowptr[N_NODES + 1];
__device__ int   g_cursor[N_NODES];
__device__ int   g_csrc  [N_EDGES];

// ---------------- small utility kernels --------------------------------------
__global__ void zero_int_kernel(int* p, int n) {
    int i = blockIdx.x * blockDim.x + threadIdx.x;
    if (i < n) p[i] = 0;
}
__global__ void zero_float_kernel(float* p, int n) {
    int i = blockIdx.x * blockDim.x + threadIdx.x;
    if (i < n) p[i] = 0.0f;
}

// reshape Wt[l][t][c] -> Wtall[t][l*256+c]
__global__ void reshape_wt_kernel(const float* __restrict__ Wt, float* __restrict__ Wtall) {
    int i = blockIdx.x * blockDim.x + threadIdx.x;
    if (i >= L_LAYERS * T_DIM * C_DIM) return;
    int c = i % C_DIM;
    int t = (i / C_DIM) % T_DIM;
    int l = i / (C_DIM * T_DIM);
    Wtall[t * TP_LD + l * C_DIM + c] = Wt[i];
}

// ---------------- CSR build ---------------------------------------------------
__global__ void count_kernel(const int* __restrict__ dst, int* __restrict__ cnt) {
    int e = blockIdx.x * blockDim.x + threadIdx.x;
    if (e < N_EDGES) atomicAdd(&cnt[dst[e]], 1);
}

__global__ void scan_kernel(const int* __restrict__ cnt,
                            int* __restrict__ rowptr, int* __restrict__ cursor) {
    const int PER = (N_NODES + 1023) / 1024;   // 20
    int tid = threadIdx.x;
    int s0 = tid * PER;
    int vals[PER];
    int local = 0;
#pragma unroll
    for (int k = 0; k < PER; k++) {
        int i = s0 + k;
        vals[k] = (i < N_NODES) ? cnt[i] : 0;
        local += vals[k];
    }
    int lane = tid & 31, w = tid >> 5;
    int x = local;
#pragma unroll
    for (int off = 1; off < 32; off <<= 1) {
        int t = __shfl_up_sync(0xFFFFFFFFu, x, off);
        if (lane >= off) x += t;
    }
    __shared__ int wsum[32];
    if (lane == 31) wsum[w] = x;
    __syncthreads();
    if (w == 0) {
        int y = wsum[lane];
#pragma unroll
        for (int off = 1; off < 32; off <<= 1) {
            int t = __shfl_up_sync(0xFFFFFFFFu, y, off);
            if (lane >= off) y += t;
        }
        wsum[lane] = y;
    }
    __syncthreads();
    int warpoff = (w > 0) ? wsum[w - 1] : 0;
    int excl = warpoff + x - local;
#pragma unroll
    for (int k = 0; k < PER; k++) {
        int i = s0 + k;
        if (i < N_NODES) { rowptr[i] = excl; cursor[i] = excl; }
        excl += vals[k];
    }
    if (tid == 1023) rowptr[N_NODES] = warpoff + x;
}

__global__ void scatter_kernel(const int* __restrict__ src, const int* __restrict__ dst,
                               int* __restrict__ cursor, int* __restrict__ csrc) {
    int e = blockIdx.x * blockDim.x + threadIdx.x;
    if (e < N_EDGES) {
        int pos = atomicAdd(&cursor[dst[e]], 1);
        csrc[pos] = src[e];
    }
}

// ---------------- k/v for all layers ------------------------------------------
// block b: l = b/MS, m = b%MS; thread c.
__global__ void kvall_kernel(const float* __restrict__ mem, const float* __restrict__ Wk,
                             const float* __restrict__ Wv,
                             float* __restrict__ kall, float* __restrict__ vall) {
    __shared__ float sm[MD_DIM];
    int l = blockIdx.x / MS_SLOTS;
    int m = blockIdx.x % MS_SLOTS;
    int c = threadIdx.x;
    for (int i = threadIdx.x; i < MD_DIM; i += blockDim.x) sm[i] = mem[m * MD_DIM + i];
    __syncthreads();
    const float* wk = Wk + (size_t)l * MD_DIM * C_DIM;
    const float* wv = Wv + (size_t)l * MD_DIM * C_DIM;
    float ak = 0.f, av = 0.f;
#pragma unroll 4
    for (int t = 0; t < MD_DIM; t++) {
        float mv = sm[t];
        ak += mv * wk[t * C_DIM + c];
        av += mv * wv[t * C_DIM + c];
    }
    kall[(size_t)blockIdx.x * C_DIM + c] = ak;
    vall[(size_t)blockIdx.x * C_DIM + c] = av;
}

// Pt[l][m][c] = sum_c2 Wq[l][c][c2] * k[l][m][c2]
__global__ void ptall_kernel(const float* __restrict__ Wq, const float* __restrict__ kall,
                             float* __restrict__ Ptall) {
    __shared__ float sk[C_DIM];
    int l = blockIdx.x / MS_SLOTS;
    int c = threadIdx.x;
    for (int i = threadIdx.x; i < C_DIM; i += blockDim.x)
        sk[i] = kall[(size_t)blockIdx.x * C_DIM + i];
    __syncthreads();
    const float* wq = Wq + (size_t)l * C_DIM * C_DIM + (size_t)c * C_DIM;
    float acc = 0.f;
#pragma unroll 4
    for (int c2 = 0; c2 < C_DIM; c2++) acc += wq[c2] * sk[c2];
    Ptall[(size_t)blockIdx.x * C_DIM + c] = acc;
}

// ---------------- TF32 tensor-core GEMM, cp.async 3-stage ---------------------
// C[MxN] = A[MxK] @ B[KxN] with fused epilogues.
// epi 0: plain store
// epi 1: node = relu(acc + bias[col]) -> C ; XT = node + TP[r*tp_ld+col]
// epi 3: store acc -> C ; fused es/ed = per-head dot with a_s/a_d
// REQUIRES: M % 160 == 0, N % 128 == 0, K % 16 == 0.
#define TBM 160
#define TBN 128
#define TBK 16
#define NSTAGE 3
#define ASTRIDE 20
#define BSTRIDE 136
#define A_STAGE (TBM * ASTRIDE)
#define B_STAGE (TBK * BSTRIDE)
#define SMEM_FLOATS (NSTAGE * (A_STAGE + B_STAGE))

__device__ __forceinline__ uint32_t f2tf32(float x) {
    uint32_t u;
    asm("cvt.rna.tf32.f32 %0, %1;" : "=r"(u) : "f"(x));
    return u;
}

__device__ __forceinline__ void mma_tf32(float* c, const uint32_t* a, const uint32_t* b) {
    asm volatile(
        "mma.sync.aligned.m16n8k8.row.col.f32.tf32.tf32.f32 "
        "{%0,%1,%2,%3}, {%4,%5,%6,%7}, {%8,%9}, {%0,%1,%2,%3};\n"
        : "+f"(c[0]), "+f"(c[1]), "+f"(c[2]), "+f"(c[3])
        : "r"(a[0]), "r"(a[1]), "r"(a[2]), "r"(a[3]), "r"(b[0]), "r"(b[1]));
}

__device__ __forceinline__ void cp_async16(float* dst_smem, const float* src) {
    uint32_t d = (uint32_t)__cvta_generic_to_shared(dst_smem);
    asm volatile("cp.async.cg.shared.global [%0], [%1], 16;\n" :: "r"(d), "l"(src));
}
__device__ __forceinline__ void cp_commit() {
    asm volatile("cp.async.commit_group;\n");
}
template <int NN>
__device__ __forceinline__ void cp_wait() {
    asm volatile("cp.async.wait_group %0;\n" :: "n"(NN));
}

__global__ __launch_bounds__(256, 2)
void tgemm_kernel(const float* __restrict__ A, const float* __restrict__ B,
                  const float* __restrict__ bias,
                  const float* __restrict__ TP, int tp_ld, float* __restrict__ XT,
                  const float* __restrict__ Asv, const float* __restrict__ Adv,
                  float* __restrict__ es, float* __restrict__ ed,
                  float* __restrict__ C, int M, int Nn, int K, int epi) {
    extern __shared__ float smem[];
    float* As = smem;
    float* Bs = smem + NSTAGE * A_STAGE;

    int tid = threadIdx.x;
    int lane = tid & 31;
    int wid = tid >> 5;
    int wm = wid >> 2;
    int wn = wid & 3;
    int tg = lane & 3;
    int gid = lane >> 2;

    int bm = blockIdx.y * TBM;
    int bn = blockIdx.x * TBN;
    int nk = K / TBK;

    int b_r = tid >> 4;
    int b_c = (tid & 15) * 8;
    const float* a_src_base = A + (size_t)(bm + tid) * K;
    const float* b_src_base = B + (size_t)b_r * Nn + bn + b_c;

#pragma unroll
    for (int s = 0; s < 2; s++) {
        int k0 = s * TBK;
        if (s < nk) {
            if (tid < TBM) {
                float* ad = As + s * A_STAGE + tid * ASTRIDE;
                const float* asrc = a_src_base + k0;
#pragma unroll
                for (int j = 0; j < 4; j++) cp_async16(ad + j * 4, asrc + j * 4);
            }
            float* bd = Bs + s * B_STAGE + b_r * BSTRIDE + b_c;
            const float* bsrc = b_src_base + (size_t)k0 * Nn;
            cp_async16(bd, bsrc);
            cp_async16(bd + 4, bsrc + 4);
        }
        cp_commit();
    }

    float acc[5][4][4];
#pragma unroll
    for (int mt = 0; mt < 5; mt++)
#pragma unroll
        for (int nt = 0; nt < 4; nt++)
#pragma unroll
            for (int r = 0; r < 4; r++) acc[mt][nt][r] = 0.f;

    for (int kt = 0; kt < nk; kt++) {
        cp_wait<1>();
        __syncthreads();

        const float* as = As + (kt % 3) * A_STAGE;
        const float* bs = Bs + (kt % 3) * B_STAGE;

#pragma unroll
        for (int ks = 0; ks < TBK; ks += 8) {
            uint32_t bf[4][2];
#pragma unroll
            for (int nt = 0; nt < 4; nt++) {
                int n0 = wn * 32 + nt * 8 + gid;
                bf[nt][0] = f2tf32(bs[(ks + tg) * BSTRIDE + n0]);
                bf[nt][1] = f2tf32(bs[(ks + tg + 4) * BSTRIDE + n0]);
            }
#pragma unroll
            for (int mt = 0; mt < 5; mt++) {
                int m0 = wm * 80 + mt * 16 + gid;
                uint32_t af[4];
                af[0] = f2tf32(as[m0 * ASTRIDE + ks + tg]);
                af[1] = f2tf32(as[(m0 + 8) * ASTRIDE + ks + tg]);
                af[2] = f2tf32(as[m0 * ASTRIDE + ks + tg + 4]);
                af[3] = f2tf32(as[(m0 + 8) * ASTRIDE + ks + tg + 4]);
#pragma unroll
                for (int nt = 0; nt < 4; nt++)
                    mma_tf32(acc[mt][nt], af, bf[nt]);
            }
        }

        int s = (kt + 2) % 3;
        if (kt + 2 < nk) {
            int k0 = (kt + 2) * TBK;
            if (tid < TBM) {
                float* ad = As + s * A_STAGE + tid * ASTRIDE;
                const float* asrc = a_src_base + k0;
#pragma unroll
                for (int j = 0; j < 4; j++) cp_async16(ad + j * 4, asrc + j * 4);
            }
            float* bd = Bs + s * B_STAGE + b_r * BSTRIDE + b_c;
            const float* bsrc = b_src_base + (size_t)k0 * Nn;
            cp_async16(bd, bsrc);
            cp_async16(bd + 4, bsrc + 4);
        }
        cp_commit();
    }

    // ---- epilogue ----
    float as_c[8], ad_c[8];
    if (epi == 3) {
#pragma unroll
        for (int nt = 0; nt < 4; nt++) {
            int c = bn + wn * 32 + nt * 8 + tg * 2;
            as_c[nt * 2]     = Asv[c];
            as_c[nt * 2 + 1] = Asv[c + 1];
            ad_c[nt * 2]     = Adv[c];
            ad_c[nt * 2 + 1] = Adv[c + 1];
        }
    }
    int head = (bn >> 5) + wn;

#pragma unroll
    for (int mt = 0; mt < 5; mt++) {
#pragma unroll
        for (int half = 0; half < 2; half++) {
            int r = bm + wm * 80 + mt * 16 + gid + half * 8;
            float ps = 0.f, pd = 0.f;
#pragma unroll
            for (int nt = 0; nt < 4; nt++) {
                int c = bn + wn * 32 + nt * 8 + tg * 2;
                float v0 = acc[mt][nt][half * 2 + 0];
                float v1 = acc[mt][nt][half * 2 + 1];
                if (epi == 1) {
                    v0 = fmaxf(v0 + bias[c], 0.f);
                    v1 = fmaxf(v1 + bias[c + 1], 0.f);
                    const float2 tp = *reinterpret_cast<const float2*>(&TP[(size_t)r * tp_ld + c]);
                    *reinterpret_cast<float2*>(&XT[(size_t)r * Nn + c]) = make_float2(v0 + tp.x, v1 + tp.y);
                } else if (epi == 3) {
                    ps += v0 * as_c[nt * 2] + v1 * as_c[nt * 2 + 1];
                    pd += v0 * ad_c[nt * 2] + v1 * ad_c[nt * 2 + 1];
                }
                *reinterpret_cast<float2*>(&C[(size_t)r * Nn + c]) = make_float2(v0, v1);
            }
            if (epi == 3) {
                ps += __shfl_xor_sync(0xFFFFFFFFu, ps, 1);
                ps += __shfl_xor_sync(0xFFFFFFFFu, ps, 2);
                pd += __shfl_xor_sync(0xFFFFFFFFu, pd, 1);
                pd += __shfl_xor_sync(0xFFFFFFFFu, pd, 2);
                if (tg == 0) {
                    es[r * H_HEADS + head] = ps;
                    ed[r * H_HEADS + head] = pd;
                }
            }
        }
    }
}

// ---------------- edge aggregation --------------------------------------------
__global__ __launch_bounds__(256)
void edge_agg_kernel(const float* __restrict__ h, const int* __restrict__ rowptr,
                     const int* __restrict__ csrc, const float* __restrict__ es,
                     const float* __restrict__ ed, float* __restrict__ out) {
    __shared__ float sw[8][32][8];
    __shared__ int   ss[8][32];
    int warp = threadIdx.x >> 5, lane = threadIdx.x & 31;
    int n = blockIdx.x * 8 + warp;
    if (n >= N_NODES) return;
    int beg = rowptr[n], end = rowptr[n + 1];

    float edn[8];
#pragma unroll
    for (int j = 0; j < 8; j++) edn[j] = ed[n * 8 + j];

    float mh[8];
#pragma unroll
    for (int j = 0; j < 8; j++) mh[j] = -1e30f;
    for (int i = beg + lane; i < end; i += 32) {
        int s = csrc[i];
#pragma unroll
        for (int j = 0; j < 8; j++) {
            float lg = es[s * 8 + j] + edn[j];
            lg = (lg > 0.f) ? lg : NEG_SLOPE * lg;
            mh[j] = fmaxf(mh[j], lg);
        }
    }
#pragma unroll
    for (int off = 16; off > 0; off >>= 1)
#pragma unroll
        for (int j = 0; j < 8; j++) mh[j] = fmaxf(mh[j], __shfl_xor_sync(0xFFFFFFFFu, mh[j], off));

    int head = lane >> 2;
    float acc[8];
#pragma unroll
    for (int k = 0; k < 8; k++) acc[k] = 0.f;
    float dsum[8];
#pragma unroll
    for (int j = 0; j < 8; j++) dsum[j] = 0.f;

    for (int base = beg; base < end; base += 32) {
        int i = base + lane;
        int s = -1;
        float w[8];
        if (i < end) {
            s = csrc[i];
#pragma unroll
            for (int j = 0; j < 8; j++) {
                float lg = es[s * 8 + j] + edn[j];
                lg = (lg > 0.f) ? lg : NEG_SLOPE * lg;
                w[j] = __expf(lg - mh[j]);
                dsum[j] += w[j];
            }
        } else {
#pragma unroll
            for (int j = 0; j < 8; j++) w[j] = 0.f;
        }
        ss[warp][lane] = s;
#pragma unroll
        for (int j = 0; j < 8; j++) sw[warp][lane][j] = w[j];
        __syncwarp();
        int cnt = min(32, end - base);
        for (int e2 = 0; e2 < cnt; e2++) {
            int se = ss[warp][e2];
            float we = sw[warp][e2][head];
            const float4* hp = reinterpret_cast<const float4*>(&h[(size_t)se * C_DIM + lane * 8]);
            float4 h0 = hp[0], h1 = hp[1];
            acc[0] += we * h0.x; acc[1] += we * h0.y; acc[2] += we * h0.z; acc[3] += we * h0.w;
            acc[4] += we * h1.x; acc[5] += we * h1.y; acc[6] += we * h1.z; acc[7] += we * h1.w;
        }
        __syncwarp();
    }
#pragma unroll
    for (int off = 16; off > 0; off >>= 1)
#pragma unroll
        for (int j = 0; j < 8; j++) dsum[j] += __shfl_xor_sync(0xFFFFFFFFu, dsum[j], off);

    float inv = 1.0f / (dsum[head] + 1e-16f);
    float4 o0, o1;
    o0.x = fmaxf(acc[0] * inv, 0.f); o0.y = fmaxf(acc[1] * inv, 0.f);
    o0.z = fmaxf(acc[2] * inv, 0.f); o0.w = fmaxf(acc[3] * inv, 0.f);
    o1.x = fmaxf(acc[4] * inv, 0.f); o1.y = fmaxf(acc[5] * inv, 0.f);
    o1.z = fmaxf(acc[6] * inv, 0.f); o1.w = fmaxf(acc[7] * inv, 0.f);
    float4* op = reinterpret_cast<float4*>(&out[(size_t)n * C_DIM + lane * 8]);
    op[0] = o0; op[1] = o1;
}

// ---------------- fused memory cross-attention ---------------------------------
// scores[m] = (mid . Pt[m]) / sqrt(C); node = relu(mid + attn@v + xin);
// xt_next = node + tp_next (if tp_next != null)
__global__ __launch_bounds__(256)
void mem_attn_kernel(const float* __restrict__ mid, const float* __restrict__ xin,
                     const float* __restrict__ Pt, const float* __restrict__ vb,
                     const float* __restrict__ tpn,
                     float* __restrict__ node_out, float* __restrict__ xt_out) {
    __shared__ float sp[MS_SLOTS][C_DIM];
    __shared__ float sv[MS_SLOTS][C_DIM];
    for (int i = threadIdx.x; i < MS_SLOTS * C_DIM; i += blockDim.x) {
        (&sp[0][0])[i] = Pt[i];
        (&sv[0][0])[i] = vb[i];
    }
    __syncthreads();
    int warp = threadIdx.x >> 5, lane = threadIdx.x & 31;
    int n = blockIdx.x * 8 + warp;
    if (n >= N_NODES) return;

    const float4* mp = reinterpret_cast<const float4*>(&mid[(size_t)n * C_DIM + lane * 8]);
    float4 m0 = mp[0], m1 = mp[1];
    float s[MS_SLOTS];
#pragma unroll
    for (int m = 0; m < MS_SLOTS; m++) {
        const float4* pp = reinterpret_cast<const float4*>(&sp[m][lane * 8]);
        float4 p0 = pp[0], p1 = pp[1];
        float p = m0.x * p0.x + m0.y * p0.y + m0.z * p0.z + m0.w * p0.w
                + m1.x * p1.x + m1.y * p1.y + m1.z * p1.z + m1.w * p1.w;
#pragma unroll
        for (int off = 16; off > 0; off >>= 1) p += __shfl_xor_sync(0xFFFFFFFFu, p, off);
        s[m] = p * 0.0625f;
    }
    float mx = s[0];
#pragma unroll
    for (int m = 1; m < MS_SLOTS; m++) mx = fmaxf(mx, s[m]);
    float sum = 0.f;
#pragma unroll
    for (int m = 0; m < MS_SLOTS; m++) { s[m] = __expf(s[m] - mx); sum += s[m]; }
    float invs = 1.0f / sum;

    const float4* xp = reinterpret_cast<const float4*>(&xin[(size_t)n * C_DIM + lane * 8]);
    float4 x0 = xp[0], x1 = xp[1];
    float acc[8] = {m0.x + x0.x, m0.y + x0.y, m0.z + x0.z, m0.w + x0.w,
                    m1.x + x1.x, m1.y + x1.y, m1.z + x1.z, m1.w + x1.w};
#pragma unroll
    for (int m = 0; m < MS_SLOTS; m++) {
        float a = s[m] * invs;
        const float4* vp = reinterpret_cast<const float4*>(&sv[m][lane * 8]);
        float4 v0 = vp[0], v1 = vp[1];
        acc[0] += a * v0.x; acc[1] += a * v0.y; acc[2] += a * v0.z; acc[3] += a * v0.w;
        acc[4] += a * v1.x; acc[5] += a * v1.y; acc[6] += a * v1.z; acc[7] += a * v1.w;
    }
#pragma unroll
    for (int j = 0; j < 8; j++) acc[j] = fmaxf(acc[j], 0.f);
    float4* op = reinterpret_cast<float4*>(&node_out[(size_t)n * C_DIM + lane * 8]);
    op[0] = make_float4(acc[0], acc[1], acc[2], acc[3]);
    op[1] = make_float4(acc[4], acc[5], acc[6], acc[7]);
    if (tpn) {
        const float4* tp = reinterpret_cast<const float4*>(&tpn[(size_t)n * TP_LD + lane * 8]);
        float4 t0 = tp[0], t1 = tp[1];
        float4* xo = reinterpret_cast<float4*>(&xt_out[(size_t)n * C_DIM + lane * 8]);
        xo[0] = make_float4(acc[0] + t0.x, acc[1] + t0.y, acc[2] + t0.z, acc[3] + t0.w);
        xo[1] = make_float4(acc[4] + t1.x, acc[5] + t1.y, acc[6] + t1.z, acc[7] + t1.w);
    }
}

// ---------------- pooling + final projection ----------------------------------
__global__ void pool_kernel(const float* __restrict__ node, float* __restrict__ pool) {
    int c = threadIdx.x;
    float acc = 0.f;
    for (int r = blockIdx.x; r < N_NODES; r += gridDim.x) acc += node[(size_t)r * C_DIM + c];
    atomicAdd(&pool[c], acc);
}

__global__ void final_kernel(const float* __restrict__ pool, const float* __restrict__ mem,
                             const float* __restrict__ Wc, const float* __restrict__ bc,
                             float* __restrict__ out) {
    __shared__ float s0[512], s1[512];
    int i = threadIdx.x;
    float val = 0.f;
    if (i < C_DIM) {
        val = pool[i] * (1.0f / (float)N_NODES);
    } else if (i < C_DIM + MD_DIM) {
        int t = i - C_DIM;
        float a = 0.f;
#pragma unroll
        for (int m = 0; m < MS_SLOTS; m++) a += mem[m * MD_DIM + t];
        val = a * (1.0f / (float)MS_SLOTS);
    }
    float c0 = 0.f, c1 = 0.f;
    if (i < C_DIM + MD_DIM) { c0 = val * Wc[i * 2 + 0]; c1 = val * Wc[i * 2 + 1]; }
    s0[i] = c0; s1[i] = c1;
    __syncthreads();
    for (int st = 256; st > 0; st >>= 1) {
        if (i < st) { s0[i] += s0[i + st]; s1[i] += s1[i + st]; }
        __syncthreads();
    }
    if (i == 0) { out[0] = s0[0] + bc[0]; out[1] = s1[0] + bc[1]; }
}

// ---------------- host launch -------------------------------------------------
static void* getsym(const void* symbol) {
    void* p = nullptr;
    cudaGetSymbolAddress(&p, symbol);
    return p;
}

extern "C" void kernel_launch(void* const* d_in, const int* in_sizes, int n_in,
                              void* d_out, int out_size) {
    const float* x    = (const float*)d_in[0];
    const int*   ei   = (const int*)  d_in[1];
    const float* te   = (const float*)d_in[2];
    const float* Wi   = (const float*)d_in[3];
    const float* bi   = (const float*)d_in[4];
    const float* Wg   = (const float*)d_in[5];
    const float* a_s  = (const float*)d_in[6];
    const float* a_d  = (const float*)d_in[7];
    const float* Wt   = (const float*)d_in[8];
    const float* Wq   = (const float*)d_in[9];
    const float* Wk   = (const float*)d_in[10];
    const float* Wv   = (const float*)d_in[11];
    const float* mem  = (const float*)d_in[12];
    const float* Wc   = (const float*)d_in[13];
    const float* bc   = (const float*)d_in[14];
    float* out = (float*)d_out;

    float* nodeA = (float*)getsym(g_nodeA);
    float* nodeB = (float*)getsym(g_nodeB);
    float* xt    = (float*)getsym(g_xt);
    float* hbuf  = (float*)getsym(g_h);
    float* midb  = (float*)getsym(g_mid);
    float* tpall = (float*)getsym(g_tpall);
    float* Wtall = (float*)getsym(g_Wtall);
    float* esb   = (float*)getsym(g_es);
    float* edb   = (float*)getsym(g_ed);
    float* kall  = (float*)getsym(g_kall);
    float* vall  = (float*)getsym(g_vall);
    float* Ptall = (float*)getsym(g_Ptall);
    float* pool  = (float*)getsym(g_pool);
    int* cnt     = (int*)getsym(g_cnt);
    int* rowptr  = (int*)getsym(g_rowptr);
    int* cursor  = (int*)getsym(g_cursor);
    int* csrc    = (int*)getsym(g_csrc);

    const int* src = ei;
    const int* dst = ei + N_EDGES;

    const int smem_bytes = SMEM_FLOATS * 4;
    static bool attr_set = false;
    if (!attr_set) {
        cudaFuncSetAttribute(tgemm_kernel, cudaFuncAttributeMaxDynamicSharedMemorySize, smem_bytes);
        attr_set = true;
    }

    // CSR build
    zero_int_kernel<<<(N_NODES + 255) / 256, 256>>>(cnt, N_NODES);
    count_kernel<<<(N_EDGES + 255) / 256, 256>>>(dst, cnt);
    scan_kernel<<<1, 1024>>>(cnt, rowptr, cursor);
    scatter_kernel<<<(N_EDGES + 255) / 256, 256>>>(src, dst, cursor, csrc);

    // precompute (k, v, Pt) for all layers + reshaped Wt
    reshape_wt_kernel<<<(L_LAYERS * T_DIM * C_DIM + 255) / 256, 256>>>(Wt, Wtall);
    kvall_kernel<<<L_LAYERS * MS_SLOTS, 256>>>(mem, Wk, Wv, kall, vall);
    ptall_kernel<<<L_LAYERS * MS_SLOTS, 256>>>(Wq, kall, Ptall);

    // tpall = te @ Wtall  [20000 x 1280]
    dim3 tp_grid(TP_LD / TBN, N_NODES / TBM);     // (10, 125)
    tgemm_kernel<<<tp_grid, 256, smem_bytes>>>(te, Wtall, nullptr, nullptr, 0, nullptr,
                                               nullptr, nullptr, nullptr, nullptr,
                                               tpall, N_NODES, TP_LD, T_DIM, 0);

    dim3 gemm_grid(C_DIM / TBN, N_NODES / TBM);   // (2, 125)

    // input projection: nodeA = relu(x @ Wi + bi); xt = nodeA + tpall[:,0:256]
    tgemm_kernel<<<gemm_grid, 256, smem_bytes>>>(x, Wi, bi, tpall, TP_LD, xt,
                                                 nullptr, nullptr, nullptr, nullptr,
                                                 nodeA, N_NODES, C_DIM, 128, 1);

    float* nin = nodeA;
    float* nout = nodeB;
    for (int l = 0; l < L_LAYERS; l++) {
        // h = xt @ Wg[l] with fused es/ed
        tgemm_kernel<<<gemm_grid, 256, smem_bytes>>>(xt, Wg + (size_t)l * C_DIM * C_DIM,
                                                     nullptr, nullptr, 0, nullptr,
                                                     a_s + l * H_HEADS * D_HEAD,
                                                     a_d + l * H_HEADS * D_HEAD, esb, edb,
                                                     hbuf, N_NODES, C_DIM, C_DIM, 3);
        edge_agg_kernel<<<(N_NODES + 7) / 8, 256>>>(hbuf, rowptr, csrc, esb, edb, midb);
        const float* tpn = (l + 1 < L_LAYERS) ? (tpall + (size_t)(l + 1) * C_DIM) : nullptr;
        mem_attn_kernel<<<(N_NODES + 7) / 8, 256>>>(midb, nin,
                                                    Ptall + (size_t)l * MS_SLOTS * C_DIM,
                                                    vall + (size_t)l * MS_SLOTS * C_DIM,
                                                    tpn, nout, xt);
        float* tmp = nin; nin = nout; nout = tmp;
    }

    zero_float_kernel<<<1, 256>>>(pool, C_DIM);
    pool_kernel<<<148, 256>>>(nin, pool);
    final_kernel<<<1, 512>>>(pool, mem, Wc, bc, out);
}

// round 5
// speedup vs baseline: 2.6483x; 1.1035x over previous
#include <cuda_runtime.h>
#include <cuda_bf16.h>
#include <cstdint>

#define N_NODES 20000
#define N_EDGES 320000
#define C_DIM   256
#define H_HEADS 8
#define D_HEAD  32
#define L_LAYERS 5
#define T_DIM   64
#define MS_SLOTS 10
#define MD_DIM  128
#define NEG_SLOPE 0.2f
#define TP_LD   (L_LAYERS * C_DIM)   // 1280

// ---------------- scratch buffers ---------------------------------------------
__device__ float g_nodeA[N_NODES * C_DIM];
__device__ float g_nodeB[N_NODES * C_DIM];
__device__ float g_xt  [N_NODES * C_DIM];
__device__ __nv_bfloat16 g_hbf[N_NODES * C_DIM];
__device__ float g_tpall[N_NODES * TP_LD];
__device__ float g_Wtall[T_DIM * TP_LD];
__device__ float g_es  [N_NODES * H_HEADS];
__device__ float g_ed  [N_NODES * H_HEADS];
__device__ float g_kall [L_LAYERS * MS_SLOTS * C_DIM];
__device__ float g_vall [L_LAYERS * MS_SLOTS * C_DIM];
__device__ float g_Ptall[L_LAYERS * MS_SLOTS * C_DIM];
__device__ float g_pool[C_DIM];
__device__ int   g_cnt   [N_NODES];
__device__ int   g_rowptr[N_NODES + 1];
__device__ int   g_cursor[N_NODES];
__device__ int   g_csrc  [N_EDGES];

// ---------------- small utility kernels --------------------------------------
__global__ void zero_int_kernel(int* p, int n) {
    int i = blockIdx.x * blockDim.x + threadIdx.x;
    if (i < n) p[i] = 0;
}
__global__ void zero_float_kernel(float* p, int n) {
    int i = blockIdx.x * blockDim.x + threadIdx.x;
    if (i < n) p[i] = 0.0f;
}

__global__ void reshape_wt_kernel(const float* __restrict__ Wt, float* __restrict__ Wtall) {
    int i = blockIdx.x * blockDim.x + threadIdx.x;
    if (i >= L_LAYERS * T_DIM * C_DIM) return;
    int c = i % C_DIM;
    int t = (i / C_DIM) % T_DIM;
    int l = i / (C_DIM * T_DIM);
    Wtall[t * TP_LD + l * C_DIM + c] = Wt[i];
}

// ---------------- CSR build ---------------------------------------------------
__global__ void count_kernel(const int* __restrict__ dst, int* __restrict__ cnt) {
    int e = blockIdx.x * blockDim.x + threadIdx.x;
    if (e < N_EDGES) atomicAdd(&cnt[dst[e]], 1);
}

__global__ void scan_kernel(const int* __restrict__ cnt,
                            int* __restrict__ rowptr, int* __restrict__ cursor) {
    const int PER = (N_NODES + 1023) / 1024;   // 20
    int tid = threadIdx.x;
    int s0 = tid * PER;
    int vals[PER];
    int local = 0;
#pragma unroll
    for (int k = 0; k < PER; k++) {
        int i = s0 + k;
        vals[k] = (i < N_NODES) ? cnt[i] : 0;
        local += vals[k];
    }
    int lane = tid & 31, w = tid >> 5;
    int x = local;
#pragma unroll
    for (int off = 1; off < 32; off <<= 1) {
        int t = __shfl_up_sync(0xFFFFFFFFu, x, off);
        if (lane >= off) x += t;
    }
    __shared__ int wsum[32];
    if (lane == 31) wsum[w] = x;
    __syncthreads();
    if (w == 0) {
        int y = wsum[lane];
#pragma unroll
        for (int off = 1; off < 32; off <<= 1) {
            int t = __shfl_up_sync(0xFFFFFFFFu, y, off);
            if (lane >= off) y += t;
        }
        wsum[lane] = y;
    }
    __syncthreads();
    int warpoff = (w > 0) ? wsum[w - 1] : 0;
    int excl = warpoff + x - local;
#pragma unroll
    for (int k = 0; k < PER; k++) {
        int i = s0 + k;
        if (i < N_NODES) { rowptr[i] = excl; cursor[i] = excl; }
        excl += vals[k];
    }
    if (tid == 1023) rowptr[N_NODES] = warpoff + x;
}

__global__ void scatter_kernel(const int* __restrict__ src, const int* __restrict__ dst,
                               int* __restrict__ cursor, int* __restrict__ csrc) {
    int e = blockIdx.x * blockDim.x + threadIdx.x;
    if (e < N_EDGES) {
        int pos = atomicAdd(&cursor[dst[e]], 1);
        csrc[pos] = src[e];
    }
}

// ---------------- k/v/Pt for all layers ---------------------------------------
__global__ void kvall_kernel(const float* __restrict__ mem, const float* __restrict__ Wk,
                             const float* __restrict__ Wv,
                             float* __restrict__ kall, float* __restrict__ vall) {
    __shared__ float sm[MD_DIM];
    int l = blockIdx.x / MS_SLOTS;
    int m = blockIdx.x % MS_SLOTS;
    int c = threadIdx.x;
    for (int i = threadIdx.x; i < MD_DIM; i += blockDim.x) sm[i] = mem[m * MD_DIM + i];
    __syncthreads();
    const float* wk = Wk + (size_t)l * MD_DIM * C_DIM;
    const float* wv = Wv + (size_t)l * MD_DIM * C_DIM;
    float ak = 0.f, av = 0.f;
#pragma unroll 4
    for (int t = 0; t < MD_DIM; t++) {
        float mv = sm[t];
        ak += mv * wk[t * C_DIM + c];
        av += mv * wv[t * C_DIM + c];
    }
    kall[(size_t)blockIdx.x * C_DIM + c] = ak;
    vall[(size_t)blockIdx.x * C_DIM + c] = av;
}

__global__ void ptall_kernel(const float* __restrict__ Wq, const float* __restrict__ kall,
                             float* __restrict__ Ptall) {
    __shared__ float sk[C_DIM];
    int l = blockIdx.x / MS_SLOTS;
    int c = threadIdx.x;
    for (int i = threadIdx.x; i < C_DIM; i += blockDim.x)
        sk[i] = kall[(size_t)blockIdx.x * C_DIM + i];
    __syncthreads();
    const float* wq = Wq + (size_t)l * C_DIM * C_DIM + (size_t)c * C_DIM;
    float acc = 0.f;
#pragma unroll 4
    for (int c2 = 0; c2 < C_DIM; c2++) acc += wq[c2] * sk[c2];
    Ptall[(size_t)blockIdx.x * C_DIM + c] = acc;
}

// ---------------- TF32 tensor-core GEMM, cp.async 3-stage ---------------------
// epi 0: plain fp32 store to C
// epi 1: node = relu(acc + bias[col]) -> C ; XT = node + TP[r*tp_ld+col]
// epi 3: store acc as bf16 -> (bf16*)C ; fused es/ed per-head dots
#define TBM 160
#define TBN 128
#define TBK 16
#define NSTAGE 3
#define ASTRIDE 20
#define BSTRIDE 136
#define A_STAGE (TBM * ASTRIDE)
#define B_STAGE (TBK * BSTRIDE)
#define SMEM_FLOATS (NSTAGE * (A_STAGE + B_STAGE))

__device__ __forceinline__ uint32_t f2tf32(float x) {
    uint32_t u;
    asm("cvt.rna.tf32.f32 %0, %1;" : "=r"(u) : "f"(x));
    return u;
}

__device__ __forceinline__ void mma_tf32(float* c, const uint32_t* a, const uint32_t* b) {
    asm volatile(
        "mma.sync.aligned.m16n8k8.row.col.f32.tf32.tf32.f32 "
        "{%0,%1,%2,%3}, {%4,%5,%6,%7}, {%8,%9}, {%0,%1,%2,%3};\n"
        : "+f"(c[0]), "+f"(c[1]), "+f"(c[2]), "+f"(c[3])
        : "r"(a[0]), "r"(a[1]), "r"(a[2]), "r"(a[3]), "r"(b[0]), "r"(b[1]));
}

__device__ __forceinline__ void cp_async16(float* dst_smem, const float* src) {
    uint32_t d = (uint32_t)__cvta_generic_to_shared(dst_smem);
    asm volatile("cp.async.cg.shared.global [%0], [%1], 16;\n" :: "r"(d), "l"(src));
}
__device__ __forceinline__ void cp_commit() {
    asm volatile("cp.async.commit_group;\n");
}
template <int NN>
__device__ __forceinline__ void cp_wait() {
    asm volatile("cp.async.wait_group %0;\n" :: "n"(NN));
}

__global__ __launch_bounds__(256, 2)
void tgemm_kernel(const float* __restrict__ A, const float* __restrict__ B,
                  const float* __restrict__ bias,
                  const float* __restrict__ TP, int tp_ld, float* __restrict__ XT,
                  const float* __restrict__ Asv, const float* __restrict__ Adv,
                  float* __restrict__ es, float* __restrict__ ed,
                  float* __restrict__ C, int M, int Nn, int K, int epi) {
    extern __shared__ float smem[];
    float* As = smem;
    float* Bs = smem + NSTAGE * A_STAGE;

    int tid = threadIdx.x;
    int lane = tid & 31;
    int wid = tid >> 5;
    int wm = wid >> 2;
    int wn = wid & 3;
    int tg = lane & 3;
    int gid = lane >> 2;

    int bm = blockIdx.y * TBM;
    int bn = blockIdx.x * TBN;
    int nk = K / TBK;

    int b_r = tid >> 4;
    int b_c = (tid & 15) * 8;
    const float* a_src_base = A + (size_t)(bm + tid) * K;
    const float* b_src_base = B + (size_t)b_r * Nn + bn + b_c;

#pragma unroll
    for (int s = 0; s < 2; s++) {
        int k0 = s * TBK;
        if (s < nk) {
            if (tid < TBM) {
                float* ad = As + s * A_STAGE + tid * ASTRIDE;
                const float* asrc = a_src_base + k0;
#pragma unroll
                for (int j = 0; j < 4; j++) cp_async16(ad + j * 4, asrc + j * 4);
            }
            float* bd = Bs + s * B_STAGE + b_r * BSTRIDE + b_c;
            const float* bsrc = b_src_base + (size_t)k0 * Nn;
            cp_async16(bd, bsrc);
            cp_async16(bd + 4, bsrc + 4);
        }
        cp_commit();
    }

    float acc[5][4][4];
#pragma unroll
    for (int mt = 0; mt < 5; mt++)
#pragma unroll
        for (int nt = 0; nt < 4; nt++)
#pragma unroll
            for (int r = 0; r < 4; r++) acc[mt][nt][r] = 0.f;

    for (int kt = 0; kt < nk; kt++) {
        cp_wait<1>();
        __syncthreads();

        const float* as = As + (kt % 3) * A_STAGE;
        const float* bs = Bs + (kt % 3) * B_STAGE;

#pragma unroll
        for (int ks = 0; ks < TBK; ks += 8) {
            uint32_t bf[4][2];
#pragma unroll
            for (int nt = 0; nt < 4; nt++) {
                int n0 = wn * 32 + nt * 8 + gid;
                bf[nt][0] = f2tf32(bs[(ks + tg) * BSTRIDE + n0]);
                bf[nt][1] = f2tf32(bs[(ks + tg + 4) * BSTRIDE + n0]);
            }
#pragma unroll
            for (int mt = 0; mt < 5; mt++) {
                int m0 = wm * 80 + mt * 16 + gid;
                uint32_t af[4];
                af[0] = f2tf32(as[m0 * ASTRIDE + ks + tg]);
                af[1] = f2tf32(as[(m0 + 8) * ASTRIDE + ks + tg]);
                af[2] = f2tf32(as[m0 * ASTRIDE + ks + tg + 4]);
                af[3] = f2tf32(as[(m0 + 8) * ASTRIDE + ks + tg + 4]);
#pragma unroll
                for (int nt = 0; nt < 4; nt++)
                    mma_tf32(acc[mt][nt], af, bf[nt]);
            }
        }

        int s = (kt + 2) % 3;
        if (kt + 2 < nk) {
            int k0 = (kt + 2) * TBK;
            if (tid < TBM) {
                float* ad = As + s * A_STAGE + tid * ASTRIDE;
                const float* asrc = a_src_base + k0;
#pragma unroll
                for (int j = 0; j < 4; j++) cp_async16(ad + j * 4, asrc + j * 4);
            }
            float* bd = Bs + s * B_STAGE + b_r * BSTRIDE + b_c;
            const float* bsrc = b_src_base + (size_t)k0 * Nn;
            cp_async16(bd, bsrc);
            cp_async16(bd + 4, bsrc + 4);
        }
        cp_commit();
    }

    // ---- epilogue ----
    float as_c[8], ad_c[8];
    if (epi == 3) {
#pragma unroll
        for (int nt = 0; nt < 4; nt++) {
            int c = bn + wn * 32 + nt * 8 + tg * 2;
            as_c[nt * 2]     = Asv[c];
            as_c[nt * 2 + 1] = Asv[c + 1];
            ad_c[nt * 2]     = Adv[c];
            ad_c[nt * 2 + 1] = Adv[c + 1];
        }
    }
    int head = (bn >> 5) + wn;
    __nv_bfloat16* Hbf = reinterpret_cast<__nv_bfloat16*>(C);

#pragma unroll
    for (int mt = 0; mt < 5; mt++) {
#pragma unroll
        for (int half = 0; half < 2; half++) {
            int r = bm + wm * 80 + mt * 16 + gid + half * 8;
            float ps = 0.f, pd = 0.f;
#pragma unroll
            for (int nt = 0; nt < 4; nt++) {
                int c = bn + wn * 32 + nt * 8 + tg * 2;
                float v0 = acc[mt][nt][half * 2 + 0];
                float v1 = acc[mt][nt][half * 2 + 1];
                if (epi == 1) {
                    v0 = fmaxf(v0 + bias[c], 0.f);
                    v1 = fmaxf(v1 + bias[c + 1], 0.f);
                    const float2 tp = *reinterpret_cast<const float2*>(&TP[(size_t)r * tp_ld + c]);
                    *reinterpret_cast<float2*>(&XT[(size_t)r * Nn + c]) = make_float2(v0 + tp.x, v1 + tp.y);
                    *reinterpret_cast<float2*>(&C[(size_t)r * Nn + c]) = make_float2(v0, v1);
                } else if (epi == 3) {
                    ps += v0 * as_c[nt * 2] + v1 * as_c[nt * 2 + 1];
                    pd += v0 * ad_c[nt * 2] + v1 * ad_c[nt * 2 + 1];
                    *reinterpret_cast<__nv_bfloat162*>(&Hbf[(size_t)r * Nn + c]) =
                        __floats2bfloat162_rn(v0, v1);
                } else {
                    *reinterpret_cast<float2*>(&C[(size_t)r * Nn + c]) = make_float2(v0, v1);
                }
            }
            if (epi == 3) {
                ps += __shfl_xor_sync(0xFFFFFFFFu, ps, 1);
                ps += __shfl_xor_sync(0xFFFFFFFFu, ps, 2);
                pd += __shfl_xor_sync(0xFFFFFFFFu, pd, 1);
                pd += __shfl_xor_sync(0xFFFFFFFFu, pd, 2);
                if (tg == 0) {
                    es[r * H_HEADS + head] = ps;
                    ed[r * H_HEADS + head] = pd;
                }
            }
        }
    }
}

// ---------------- fused edge aggregation + memory cross-attention --------------
// Per warp (one node): GAT softmax-aggregate over bf16 h, then memory attention
// via precomputed Pt (scores = mid.Pt[m]/16), softmax over 10 slots, blend v,
// residual + relu -> node_out; xt_out = node_out + tp_next (if tpn).
__global__ __launch_bounds__(256)
void edge_mem_kernel(const __nv_bfloat16* __restrict__ h, const int* __restrict__ rowptr,
                     const int* __restrict__ csrc, const float* __restrict__ es,
                     const float* __restrict__ ed,
                     const float* __restrict__ Pt, const float* __restrict__ vb,
                     const float* __restrict__ xin, const float* __restrict__ tpn,
                     float* __restrict__ node_out, float* __restrict__ xt_out) {
    __shared__ float sp[MS_SLOTS][C_DIM];
    __shared__ float sv[MS_SLOTS][C_DIM];
    __shared__ float sw[8][32][8];
    __shared__ int   ss[8][32];
    for (int i = threadIdx.x; i < MS_SLOTS * C_DIM; i += blockDim.x) {
        (&sp[0][0])[i] = Pt[i];
        (&sv[0][0])[i] = vb[i];
    }
    __syncthreads();

    int warp = threadIdx.x >> 5, lane = threadIdx.x & 31;
    int n = blockIdx.x * 8 + warp;
    if (n >= N_NODES) return;
    int beg = rowptr[n], end = rowptr[n + 1];

    float edn[8];
#pragma unroll
    for (int j = 0; j < 8; j++) edn[j] = ed[n * 8 + j];

    // pass 1: per-head max
    float mh[8];
#pragma unroll
    for (int j = 0; j < 8; j++) mh[j] = -1e30f;
    for (int i = beg + lane; i < end; i += 32) {
        int s = csrc[i];
#pragma unroll
        for (int j = 0; j < 8; j++) {
            float lg = es[s * 8 + j] + edn[j];
            lg = (lg > 0.f) ? lg : NEG_SLOPE * lg;
            mh[j] = fmaxf(mh[j], lg);
        }
    }
#pragma unroll
    for (int off = 16; off > 0; off >>= 1)
#pragma unroll
        for (int j = 0; j < 8; j++) mh[j] = fmaxf(mh[j], __shfl_xor_sync(0xFFFFFFFFu, mh[j], off));

    int head = lane >> 2;
    float acc[8];
#pragma unroll
    for (int k = 0; k < 8; k++) acc[k] = 0.f;
    float dsum[8];
#pragma unroll
    for (int j = 0; j < 8; j++) dsum[j] = 0.f;

    for (int base = beg; base < end; base += 32) {
        int i = base + lane;
        int s = -1;
        float w[8];
        if (i < end) {
            s = csrc[i];
#pragma unroll
            for (int j = 0; j < 8; j++) {
                float lg = es[s * 8 + j] + edn[j];
                lg = (lg > 0.f) ? lg : NEG_SLOPE * lg;
                w[j] = __expf(lg - mh[j]);
                dsum[j] += w[j];
            }
        } else {
#pragma unroll
            for (int j = 0; j < 8; j++) w[j] = 0.f;
        }
        ss[warp][lane] = s;
#pragma unroll
        for (int j = 0; j < 8; j++) sw[warp][lane][j] = w[j];
        __syncwarp();
        int cnt = min(32, end - base);
        for (int e2 = 0; e2 < cnt; e2++) {
            int se = ss[warp][e2];
            float we = sw[warp][e2][head];
            uint4 hv = *reinterpret_cast<const uint4*>(&h[(size_t)se * C_DIM + lane * 8]);
            float2 f0 = __bfloat1622float2(*reinterpret_cast<__nv_bfloat162*>(&hv.x));
            float2 f1 = __bfloat1622float2(*reinterpret_cast<__nv_bfloat162*>(&hv.y));
            float2 f2 = __bfloat1622float2(*reinterpret_cast<__nv_bfloat162*>(&hv.z));
            float2 f3 = __bfloat1622float2(*reinterpret_cast<__nv_bfloat162*>(&hv.w));
            acc[0] += we * f0.x; acc[1] += we * f0.y;
            acc[2] += we * f1.x; acc[3] += we * f1.y;
            acc[4] += we * f2.x; acc[5] += we * f2.y;
            acc[6] += we * f3.x; acc[7] += we * f3.y;
        }
        __syncwarp();
    }
#pragma unroll
    for (int off = 16; off > 0; off >>= 1)
#pragma unroll
        for (int j = 0; j < 8; j++) dsum[j] += __shfl_xor_sync(0xFFFFFFFFu, dsum[j], off);

    float inv = 1.0f / (dsum[head] + 1e-16f);
    float mid[8];
#pragma unroll
    for (int j = 0; j < 8; j++) mid[j] = fmaxf(acc[j] * inv, 0.f);

    // ---- memory cross-attention (fused) ----
    float s[MS_SLOTS];
#pragma unroll
    for (int m = 0; m < MS_SLOTS; m++) {
        const float* pr = &sp[m][lane * 8];
        float p = mid[0] * pr[0] + mid[1] * pr[1] + mid[2] * pr[2] + mid[3] * pr[3]
                + mid[4] * pr[4] + mid[5] * pr[5] + mid[6] * pr[6] + mid[7] * pr[7];
#pragma unroll
        for (int off = 16; off > 0; off >>= 1) p += __shfl_xor_sync(0xFFFFFFFFu, p, off);
        s[m] = p * 0.0625f;   // 1/sqrt(256)
    }
    float mx = s[0];
#pragma unroll
    for (int m = 1; m < MS_SLOTS; m++) mx = fmaxf(mx, s[m]);
    float sum = 0.f;
#pragma unroll
    for (int m = 0; m < MS_SLOTS; m++) { s[m] = __expf(s[m] - mx); sum += s[m]; }
    float invs = 1.0f / sum;

    const float4* xp = reinterpret_cast<const float4*>(&xin[(size_t)n * C_DIM + lane * 8]);
    float4 x0 = xp[0], x1 = xp[1];
    float o[8] = {mid[0] + x0.x, mid[1] + x0.y, mid[2] + x0.z, mid[3] + x0.w,
                  mid[4] + x1.x, mid[5] + x1.y, mid[6] + x1.z, mid[7] + x1.w};
#pragma unroll
    for (int m = 0; m < MS_SLOTS; m++) {
        float a = s[m] * invs;
        const float4* vp = reinterpret_cast<const float4*>(&sv[m][lane * 8]);
        float4 v0 = vp[0], v1 = vp[1];
        o[0] += a * v0.x; o[1] += a * v0.y; o[2] += a * v0.z; o[3] += a * v0.w;
        o[4] += a * v1.x; o[5] += a * v1.y; o[6] += a * v1.z; o[7] += a * v1.w;
    }
#pragma unroll
    for (int j = 0; j < 8; j++) o[j] = fmaxf(o[j], 0.f);
    float4* op = reinterpret_cast<float4*>(&node_out[(size_t)n * C_DIM + lane * 8]);
    op[0] = make_float4(o[0], o[1], o[2], o[3]);
    op[1] = make_float4(o[4], o[5], o[6], o[7]);
    if (tpn) {
        const float4* tp = reinterpret_cast<const float4*>(&tpn[(size_t)n * TP_LD + lane * 8]);
        float4 t0 = tp[0], t1 = tp[1];
        float4* xo = reinterpret_cast<float4*>(&xt_out[(size_t)n * C_DIM + lane * 8]);
        xo[0] = make_float4(o[0] + t0.x, o[1] + t0.y, o[2] + t0.z, o[3] + t0.w);
        xo[1] = make_float4(o[4] + t1.x, o[5] + t1.y, o[6] + t1.z, o[7] + t1.w);
    }
}

// ---------------- pooling + final projection ----------------------------------
__global__ void pool_kernel(const float* __restrict__ node, float* __restrict__ pool) {
    int c = threadIdx.x;
    float acc = 0.f;
    for (int r = blockIdx.x; r < N_NODES; r += gridDim.x) acc += node[(size_t)r * C_DIM + c];
    atomicAdd(&pool[c], acc);
}

__global__ void final_kernel(const float* __restrict__ pool, const float* __restrict__ mem,
                             const float* __restrict__ Wc, const float* __restrict__ bc,
                             float* __restrict__ out) {
    __shared__ float s0[512], s1[512];
    int i = threadIdx.x;
    float val = 0.f;
    if (i < C_DIM) {
        val = pool[i] * (1.0f / (float)N_NODES);
    } else if (i < C_DIM + MD_DIM) {
        int t = i - C_DIM;
        float a = 0.f;
#pragma unroll
        for (int m = 0; m < MS_SLOTS; m++) a += mem[m * MD_DIM + t];
        val = a * (1.0f / (float)MS_SLOTS);
    }
    float c0 = 0.f, c1 = 0.f;
    if (i < C_DIM + MD_DIM) { c0 = val * Wc[i * 2 + 0]; c1 = val * Wc[i * 2 + 1]; }
    s0[i] = c0; s1[i] = c1;
    __syncthreads();
    for (int st = 256; st > 0; st >>= 1) {
        if (i < st) { s0[i] += s0[i + st]; s1[i] += s1[i + st]; }
        __syncthreads();
    }
    if (i == 0) { out[0] = s0[0] + bc[0]; out[1] = s1[0] + bc[1]; }
}

// ---------------- host launch -------------------------------------------------
static void* getsym(const void* symbol) {
    void* p = nullptr;
    cudaGetSymbolAddress(&p, symbol);
    return p;
}

extern "C" void kernel_launch(void* const* d_in, const int* in_sizes, int n_in,
                              void* d_out, int out_size) {
    const float* x    = (const float*)d_in[0];
    const int*   ei   = (const int*)  d_in[1];
    const float* te   = (const float*)d_in[2];
    const float* Wi   = (const float*)d_in[3];
    const float* bi   = (const float*)d_in[4];
    const float* Wg   = (const float*)d_in[5];
    const float* a_s  = (const float*)d_in[6];
    const float* a_d  = (const float*)d_in[7];
    const float* Wt   = (const float*)d_in[8];
    const float* Wq   = (const float*)d_in[9];
    const float* Wk   = (const float*)d_in[10];
    const float* Wv   = (const float*)d_in[11];
    const float* mem  = (const float*)d_in[12];
    const float* Wc   = (const float*)d_in[13];
    const float* bc   = (const float*)d_in[14];
    float* out = (float*)d_out;

    float* nodeA = (float*)getsym(g_nodeA);
    float* nodeB = (float*)getsym(g_nodeB);
    float* xt    = (float*)getsym(g_xt);
    __nv_bfloat16* hbf = (__nv_bfloat16*)getsym(g_hbf);
    float* tpall = (float*)getsym(g_tpall);
    float* Wtall = (float*)getsym(g_Wtall);
    float* esb   = (float*)getsym(g_es);
    float* edb   = (float*)getsym(g_ed);
    float* kall  = (float*)getsym(g_kall);
    float* vall  = (float*)getsym(g_vall);
    float* Ptall = (float*)getsym(g_Ptall);
    float* pool  = (float*)getsym(g_pool);
    int* cnt     = (int*)getsym(g_cnt);
    int* rowptr  = (int*)getsym(g_rowptr);
    int* cursor  = (int*)getsym(g_cursor);
    int* csrc    = (int*)getsym(g_csrc);

    const int* src = ei;
    const int* dst = ei + N_EDGES;

    const int smem_bytes = SMEM_FLOATS * 4;
    static bool attr_set = false;
    if (!attr_set) {
        cudaFuncSetAttribute(tgemm_kernel, cudaFuncAttributeMaxDynamicSharedMemorySize, smem_bytes);
        attr_set = true;
    }

    // CSR build
    zero_int_kernel<<<(N_NODES + 255) / 256, 256>>>(cnt, N_NODES);
    count_kernel<<<(N_EDGES + 255) / 256, 256>>>(dst, cnt);
    scan_kernel<<<1, 1024>>>(cnt, rowptr, cursor);
    scatter_kernel<<<(N_EDGES + 255) / 256, 256>>>(src, dst, cursor, csrc);

    // precompute (k, v, Pt) for all layers + reshaped Wt
    reshape_wt_kernel<<<(L_LAYERS * T_DIM * C_DIM + 255) / 256, 256>>>(Wt, Wtall);
    kvall_kernel<<<L_LAYERS * MS_SLOTS, 256>>>(mem, Wk, Wv, kall, vall);
    ptall_kernel<<<L_LAYERS * MS_SLOTS, 256>>>(Wq, kall, Ptall);

    // tpall = te @ Wtall  [20000 x 1280]
    dim3 tp_grid(TP_LD / TBN, N_NODES / TBM);     // (10, 125)
    tgemm_kernel<<<tp_grid, 256, smem_bytes>>>(te, Wtall, nullptr, nullptr, 0, nullptr,
                                               nullptr, nullptr, nullptr, nullptr,
                                               tpall, N_NODES, TP_LD, T_DIM, 0);

    dim3 gemm_grid(C_DIM / TBN, N_NODES / TBM);   // (2, 125)

    // input projection: nodeA = relu(x @ Wi + bi); xt = nodeA + tpall[:,0:256]
    tgemm_kernel<<<gemm_grid, 256, smem_bytes>>>(x, Wi, bi, tpall, TP_LD, xt,
                                                 nullptr, nullptr, nullptr, nullptr,
                                                 nodeA, N_NODES, C_DIM, 128, 1);

    float* nin = nodeA;
    float* nout = nodeB;
    for (int l = 0; l < L_LAYERS; l++) {
        // h(bf16) = xt @ Wg[l] with fused es/ed
        tgemm_kernel<<<gemm_grid, 256, smem_bytes>>>(xt, Wg + (size_t)l * C_DIM * C_DIM,
                                                     nullptr, nullptr, 0, nullptr,
                                                     a_s + l * H_HEADS * D_HEAD,
                                                     a_d + l * H_HEADS * D_HEAD, esb, edb,
                                                     (float*)hbf, N_NODES, C_DIM, C_DIM, 3);
        const float* tpn = (l + 1 < L_LAYERS) ? (tpall + (size_t)(l + 1) * C_DIM) : nullptr;
        edge_mem_kernel<<<(N_NODES + 7) / 8, 256>>>(hbf, rowptr, csrc, esb, edb,
                                                    Ptall + (size_t)l * MS_SLOTS * C_DIM,
                                                    vall + (size_t)l * MS_SLOTS * C_DIM,
                                                    nin, tpn, nout, xt);
        float* tmp = nin; nin = nout; nout = tmp;
    }

    zero_float_kernel<<<1, 256>>>(pool, C_DIM);
    pool_kernel<<<148, 256>>>(nin, pool);
    final_kernel<<<1, 512>>>(pool, mem, Wc, bc, out);
}

// round 6
// speedup vs baseline: 2.7479x; 1.0376x over previous
#include <cuda_runtime.h>
#include <cuda_bf16.h>
#include <cstdint>

#define N_NODES 20000
#define N_EDGES 320000
#define C_DIM   256
#define H_HEADS 8
#define D_HEAD  32
#define L_LAYERS 5
#define T_DIM   64
#define MS_SLOTS 10
#define MD_DIM  128
#define NEG_SLOPE 0.2f
#define TP_LD   (L_LAYERS * C_DIM)   // 1280

// ---------------- scratch buffers ---------------------------------------------
__device__ float g_nodeA[N_NODES * C_DIM];
__device__ float g_nodeB[N_NODES * C_DIM];
__device__ __nv_bfloat16 g_xt [N_NODES * C_DIM];          // GEMM A operand (bf16)
__device__ __nv_bfloat16 g_hbf[N_NODES * C_DIM];
__device__ __nv_bfloat16 g_xbf[N_NODES * 128];            // x in bf16
__device__ __nv_bfloat16 g_tebf[N_NODES * T_DIM];         // te in bf16
__device__ float g_tpall[N_NODES * TP_LD];
__device__ float g_Wtall[T_DIM * TP_LD];
__device__ uint32_t g_Wipk [(128 / 2) * C_DIM];           // packed bf16x2 weights
__device__ uint32_t g_Wtpk [(T_DIM / 2) * TP_LD];
__device__ uint32_t g_Wgpk [L_LAYERS * (C_DIM / 2) * C_DIM];
__device__ float g_es  [N_NODES * H_HEADS];
__device__ float g_ed  [N_NODES * H_HEADS];
__device__ float g_kall [L_LAYERS * MS_SLOTS * C_DIM];
__device__ float g_vall [L_LAYERS * MS_SLOTS * C_DIM];
__device__ float g_Ptall[L_LAYERS * MS_SLOTS * C_DIM];
__device__ float g_pool[C_DIM];
__device__ int   g_cnt   [N_NODES];
__device__ int   g_rowptr[N_NODES + 1];
__device__ int   g_cursor[N_NODES];
__device__ int   g_csrc  [N_EDGES];

// ---------------- small utility kernels --------------------------------------
__global__ void zero_int_kernel(int* p, int n) {
    int i = blockIdx.x * blockDim.x + threadIdx.x;
    if (i < n) p[i] = 0;
}
__global__ void zero_float_kernel(float* p, int n) {
    int i = blockIdx.x * blockDim.x + threadIdx.x;
    if (i < n) p[i] = 0.0f;
}
__global__ void f2bf_kernel(const float* __restrict__ in, __nv_bfloat16* __restrict__ out, int n) {
    int i = blockIdx.x * blockDim.x + threadIdx.x;
    if (i < n) out[i] = __float2bfloat16(in[i]);
}
// pack W[K][N] fp32 -> out[K/2][N] u32 of bf16x2 {W[2k2][n], W[2k2+1][n]}
__global__ void pack_w_kernel(const float* __restrict__ W, uint32_t* __restrict__ out,
                              int K, int N) {
    int i = blockIdx.x * blockDim.x + threadIdx.x;
    if (i >= (K / 2) * N) return;
    int n = i % N, k2 = i / N;
    __nv_bfloat162 p = __floats2bfloat162_rn(W[(2 * k2) * N + n], W[(2 * k2 + 1) * N + n]);
    out[i] = *reinterpret_cast<uint32_t*>(&p);
}
__global__ void reshape_wt_kernel(const float* __restrict__ Wt, float* __restrict__ Wtall) {
    int i = blockIdx.x * blockDim.x + threadIdx.x;
    if (i >= L_LAYERS * T_DIM * C_DIM) return;
    int c = i % C_DIM;
    int t = (i / C_DIM) % T_DIM;
    int l = i / (C_DIM * T_DIM);
    Wtall[t * TP_LD + l * C_DIM + c] = Wt[i];
}

// ---------------- CSR build ---------------------------------------------------
__global__ void count_kernel(const int* __restrict__ dst, int* __restrict__ cnt) {
    int e = blockIdx.x * blockDim.x + threadIdx.x;
    if (e < N_EDGES) atomicAdd(&cnt[dst[e]], 1);
}

__global__ void scan_kernel(const int* __restrict__ cnt,
                            int* __restrict__ rowptr, int* __restrict__ cursor) {
    const int PER = (N_NODES + 1023) / 1024;   // 20
    int tid = threadIdx.x;
    int s0 = tid * PER;
    int vals[PER];
    int local = 0;
#pragma unroll
    for (int k = 0; k < PER; k++) {
        int i = s0 + k;
        vals[k] = (i < N_NODES) ? cnt[i] : 0;
        local += vals[k];
    }
    int lane = tid & 31, w = tid >> 5;
    int x = local;
#pragma unroll
    for (int off = 1; off < 32; off <<= 1) {
        int t = __shfl_up_sync(0xFFFFFFFFu, x, off);
        if (lane >= off) x += t;
    }
    __shared__ int wsum[32];
    if (lane == 31) wsum[w] = x;
    __syncthreads();
    if (w == 0) {
        int y = wsum[lane];
#pragma unroll
        for (int off = 1; off < 32; off <<= 1) {
            int t = __shfl_up_sync(0xFFFFFFFFu, y, off);
            if (lane >= off) y += t;
        }
        wsum[lane] = y;
    }
    __syncthreads();
    int warpoff = (w > 0) ? wsum[w - 1] : 0;
    int excl = warpoff + x - local;
#pragma unroll
    for (int k = 0; k < PER; k++) {
        int i = s0 + k;
        if (i < N_NODES) { rowptr[i] = excl; cursor[i] = excl; }
        excl += vals[k];
    }
    if (tid == 1023) rowptr[N_NODES] = warpoff + x;
}

__global__ void scatter_kernel(const int* __restrict__ src, const int* __restrict__ dst,
                               int* __restrict__ cursor, int* __restrict__ csrc) {
    int e = blockIdx.x * blockDim.x + threadIdx.x;
    if (e < N_EDGES) {
        int pos = atomicAdd(&cursor[dst[e]], 1);
        csrc[pos] = src[e];
    }
}

// ---------------- k/v/Pt for all layers ---------------------------------------
__global__ void kvall_kernel(const float* __restrict__ mem, const float* __restrict__ Wk,
                             const float* __restrict__ Wv,
                             float* __restrict__ kall, float* __restrict__ vall) {
    __shared__ float sm[MD_DIM];
    int l = blockIdx.x / MS_SLOTS;
    int m = blockIdx.x % MS_SLOTS;
    int c = threadIdx.x;
    for (int i = threadIdx.x; i < MD_DIM; i += blockDim.x) sm[i] = mem[m * MD_DIM + i];
    __syncthreads();
    const float* wk = Wk + (size_t)l * MD_DIM * C_DIM;
    const float* wv = Wv + (size_t)l * MD_DIM * C_DIM;
    float ak = 0.f, av = 0.f;
#pragma unroll 4
    for (int t = 0; t < MD_DIM; t++) {
        float mv = sm[t];
        ak += mv * wk[t * C_DIM + c];
        av += mv * wv[t * C_DIM + c];
    }
    kall[(size_t)blockIdx.x * C_DIM + c] = ak;
    vall[(size_t)blockIdx.x * C_DIM + c] = av;
}

__global__ void ptall_kernel(const float* __restrict__ Wq, const float* __restrict__ kall,
                             float* __restrict__ Ptall) {
    __shared__ float sk[C_DIM];
    int l = blockIdx.x / MS_SLOTS;
    int c = threadIdx.x;
    for (int i = threadIdx.x; i < C_DIM; i += blockDim.x)
        sk[i] = kall[(size_t)blockIdx.x * C_DIM + i];
    __syncthreads();
    const float* wq = Wq + (size_t)l * C_DIM * C_DIM + (size_t)c * C_DIM;
    float acc = 0.f;
#pragma unroll 4
    for (int c2 = 0; c2 < C_DIM; c2++) acc += wq[c2] * sk[c2];
    Ptall[(size_t)blockIdx.x * C_DIM + c] = acc;
}

// ---------------- BF16 tensor-core GEMM (m16n8k16), cp.async 4-stage ----------
// C = A[MxK](bf16, row-major) @ Bpk[K/2 x N](bf16x2-packed) ; fp32 accumulate.
// epi 0: fp32 store to Cf
// epi 1: node = relu(acc + bias[col]) -> Cf ; XT(bf16) = node + TP[r*tp_ld+col]
// epi 3: bf16 store to Cbf ; fused es/ed per-head dots
// REQUIRES: M % 160 == 0, N % 128 == 0, K % 32 == 0.
#define TBM 160
#define TBN 128
#define TBK 32
#define NSTAGE 4
#define AS32 ((TBK / 2) + 4)          // 20 u32 per A row
#define A_ST (TBM * AS32)             // 3200 u32
#define B_ST ((TBK / 2) * 136)        // 2176 u32
#define SMEM_U32 (NSTAGE * (A_ST + B_ST))   // 21504 u32 = 86016 B

__device__ __forceinline__ void mma_bf16(float* c, const uint32_t* a, const uint32_t* b) {
    asm volatile(
        "mma.sync.aligned.m16n8k16.row.col.f32.bf16.bf16.f32 "
        "{%0,%1,%2,%3}, {%4,%5,%6,%7}, {%8,%9}, {%0,%1,%2,%3};\n"
        : "+f"(c[0]), "+f"(c[1]), "+f"(c[2]), "+f"(c[3])
        : "r"(a[0]), "r"(a[1]), "r"(a[2]), "r"(a[3]), "r"(b[0]), "r"(b[1]));
}

__device__ __forceinline__ void cp_async16(void* dst_smem, const void* src) {
    uint32_t d = (uint32_t)__cvta_generic_to_shared(dst_smem);
    asm volatile("cp.async.cg.shared.global [%0], [%1], 16;\n" :: "r"(d), "l"(src));
}
__device__ __forceinline__ void cp_commit() {
    asm volatile("cp.async.commit_group;\n");
}
template <int NN>
__device__ __forceinline__ void cp_wait() {
    asm volatile("cp.async.wait_group %0;\n" :: "n"(NN));
}

__global__ __launch_bounds__(256, 2)
void bgemm_kernel(const __nv_bfloat16* __restrict__ A, const uint32_t* __restrict__ Bpk,
                  const float* __restrict__ bias,
                  const float* __restrict__ TP, int tp_ld, __nv_bfloat16* __restrict__ XT,
                  const float* __restrict__ Asv, const float* __restrict__ Adv,
                  float* __restrict__ es, float* __restrict__ ed,
                  void* __restrict__ Cout, int M, int Nn, int K, int epi) {
    extern __shared__ uint32_t smem[];
    uint32_t* As = smem;
    uint32_t* Bs = smem + NSTAGE * A_ST;

    int tid = threadIdx.x;
    int lane = tid & 31;
    int wid = tid >> 5;
    int wm = wid >> 2;          // 0..1
    int wn = wid & 3;           // 0..3
    int tg = lane & 3;
    int gid = lane >> 2;

    int bm = blockIdx.y * TBM;
    int bn = blockIdx.x * TBN;
    int nk = K / TBK;
    int K2 = Nn;                // Bpk row length in u32 == N

    int b_r = tid >> 4;         // 0..15 (k2 row within tile)
    int b_c = (tid & 15) * 8;   // u32 col
    const __nv_bfloat16* a_src_base = A + (size_t)(bm + tid) * K;
    const uint32_t* b_src_base = Bpk + (size_t)b_r * K2 + bn + b_c;

    // prologue: issue stages 0..2
#pragma unroll
    for (int s = 0; s < NSTAGE - 1; s++) {
        if (s < nk) {
            int k0 = s * TBK;
            if (tid < TBM) {
                uint32_t* ad = As + s * A_ST + tid * AS32;
                const __nv_bfloat16* asrc = a_src_base + k0;
#pragma unroll
                for (int j = 0; j < 4; j++) cp_async16(ad + j * 4, asrc + j * 8);
            }
            uint32_t* bd = Bs + s * B_ST + b_r * 136 + b_c;
            const uint32_t* bsrc = b_src_base + (size_t)(k0 / 2) * K2;
            cp_async16(bd, bsrc);
            cp_async16(bd + 4, bsrc + 4);
        }
        cp_commit();
    }

    float acc[5][4][4];
#pragma unroll
    for (int mt = 0; mt < 5; mt++)
#pragma unroll
        for (int nt = 0; nt < 4; nt++)
#pragma unroll
            for (int r = 0; r < 4; r++) acc[mt][nt][r] = 0.f;

    for (int kt = 0; kt < nk; kt++) {
        cp_wait<NSTAGE - 2>();
        __syncthreads();

        const uint32_t* as_ = As + (kt % NSTAGE) * A_ST;
        const uint32_t* bs_ = Bs + (kt % NSTAGE) * B_ST;

#pragma unroll
        for (int s = 0; s < 2; s++) {          // two k16 steps per TBK=32
            int k2q = s * 8;
            uint32_t bf[4][2];
#pragma unroll
            for (int nt = 0; nt < 4; nt++) {
                int n0 = wn * 32 + nt * 8 + gid;
                bf[nt][0] = bs_[(k2q + tg) * 136 + n0];
                bf[nt][1] = bs_[(k2q + tg + 4) * 136 + n0];
            }
#pragma unroll
            for (int mt = 0; mt < 5; mt++) {
                int m0 = wm * 80 + mt * 16 + gid;
                uint32_t af[4];
                af[0] = as_[m0 * AS32 + k2q + tg];
                af[1] = as_[(m0 + 8) * AS32 + k2q + tg];
                af[2] = as_[m0 * AS32 + k2q + tg + 4];
                af[3] = as_[(m0 + 8) * AS32 + k2q + tg + 4];
#pragma unroll
                for (int nt = 0; nt < 4; nt++)
                    mma_bf16(acc[mt][nt], af, bf[nt]);
            }
        }

        int s2 = (kt + NSTAGE - 1) % NSTAGE;
        if (kt + NSTAGE - 1 < nk) {
            int k0 = (kt + NSTAGE - 1) * TBK;
            if (tid < TBM) {
                uint32_t* ad = As + s2 * A_ST + tid * AS32;
                const __nv_bfloat16* asrc = a_src_base + k0;
#pragma unroll
                for (int j = 0; j < 4; j++) cp_async16(ad + j * 4, asrc + j * 8);
            }
            uint32_t* bd = Bs + s2 * B_ST + b_r * 136 + b_c;
            const uint32_t* bsrc = b_src_base + (size_t)(k0 / 2) * K2;
            cp_async16(bd, bsrc);
            cp_async16(bd + 4, bsrc + 4);
        }
        cp_commit();
    }

    // ---- epilogue ----
    float as_c[8], ad_c[8];
    if (epi == 3) {
#pragma unroll
        for (int nt = 0; nt < 4; nt++) {
            int c = bn + wn * 32 + nt * 8 + tg * 2;
            as_c[nt * 2]     = Asv[c];
            as_c[nt * 2 + 1] = Asv[c + 1];
            ad_c[nt * 2]     = Adv[c];
            ad_c[nt * 2 + 1] = Adv[c + 1];
        }
    }
    int head = (bn >> 5) + wn;
    float* Cf = reinterpret_cast<float*>(Cout);
    __nv_bfloat16* Cbf = reinterpret_cast<__nv_bfloat16*>(Cout);

#pragma unroll
    for (int mt = 0; mt < 5; mt++) {
#pragma unroll
        for (int half = 0; half < 2; half++) {
            int r = bm + wm * 80 + mt * 16 + gid + half * 8;
            float ps = 0.f, pd = 0.f;
#pragma unroll
            for (int nt = 0; nt < 4; nt++) {
                int c = bn + wn * 32 + nt * 8 + tg * 2;
                float v0 = acc[mt][nt][half * 2 + 0];
                float v1 = acc[mt][nt][half * 2 + 1];
                if (epi == 1) {
                    v0 = fmaxf(v0 + bias[c], 0.f);
                    v1 = fmaxf(v1 + bias[c + 1], 0.f);
                    const float2 tp = *reinterpret_cast<const float2*>(&TP[(size_t)r * tp_ld + c]);
                    __nv_bfloat162 xv = __floats2bfloat162_rn(v0 + tp.x, v1 + tp.y);
                    *reinterpret_cast<__nv_bfloat162*>(&XT[(size_t)r * Nn + c]) = xv;
                    *reinterpret_cast<float2*>(&Cf[(size_t)r * Nn + c]) = make_float2(v0, v1);
                } else if (epi == 3) {
                    ps += v0 * as_c[nt * 2] + v1 * as_c[nt * 2 + 1];
                    pd += v0 * ad_c[nt * 2] + v1 * ad_c[nt * 2 + 1];
                    *reinterpret_cast<__nv_bfloat162*>(&Cbf[(size_t)r * Nn + c]) =
                        __floats2bfloat162_rn(v0, v1);
                } else {
                    *reinterpret_cast<float2*>(&Cf[(size_t)r * Nn + c]) = make_float2(v0, v1);
                }
            }
            if (epi == 3) {
                ps += __shfl_xor_sync(0xFFFFFFFFu, ps, 1);
                ps += __shfl_xor_sync(0xFFFFFFFFu, ps, 2);
                pd += __shfl_xor_sync(0xFFFFFFFFu, pd, 1);
                pd += __shfl_xor_sync(0xFFFFFFFFu, pd, 2);
                if (tg == 0) {
                    es[r * H_HEADS + head] = ps;
                    ed[r * H_HEADS + head] = pd;
                }
            }
        }
    }
}

// ---------------- fused edge aggregation + memory cross-attention --------------
__global__ __launch_bounds__(256)
void edge_mem_kernel(const __nv_bfloat16* __restrict__ h, const int* __restrict__ rowptr,
                     const int* __restrict__ csrc, const float* __restrict__ es,
                     const float* __restrict__ ed,
                     const float* __restrict__ Pt, const float* __restrict__ vb,
                     const float* __restrict__ xin, const float* __restrict__ tpn,
                     float* __restrict__ node_out, __nv_bfloat16* __restrict__ xt_out) {
    __shared__ float sp[MS_SLOTS][C_DIM];
    __shared__ float sv[MS_SLOTS][C_DIM];
    __shared__ float sw[8][32][8];
    __shared__ int   ss[8][32];
    for (int i = threadIdx.x; i < MS_SLOTS * C_DIM; i += blockDim.x) {
        (&sp[0][0])[i] = Pt[i];
        (&sv[0][0])[i] = vb[i];
    }
    __syncthreads();

    int warp = threadIdx.x >> 5, lane = threadIdx.x & 31;
    int n = blockIdx.x * 8 + warp;
    if (n >= N_NODES) return;
    int beg = rowptr[n], end = rowptr[n + 1];

    float edn[8];
#pragma unroll
    for (int j = 0; j < 8; j++) edn[j] = ed[n * 8 + j];

    float mh[8];
#pragma unroll
    for (int j = 0; j < 8; j++) mh[j] = -1e30f;
    for (int i = beg + lane; i < end; i += 32) {
        int s = csrc[i];
#pragma unroll
        for (int j = 0; j < 8; j++) {
            float lg = es[s * 8 + j] + edn[j];
            lg = (lg > 0.f) ? lg : NEG_SLOPE * lg;
            mh[j] = fmaxf(mh[j], lg);
        }
    }
#pragma unroll
    for (int off = 16; off > 0; off >>= 1)
#pragma unroll
        for (int j = 0; j < 8; j++) mh[j] = fmaxf(mh[j], __shfl_xor_sync(0xFFFFFFFFu, mh[j], off));

    int head = lane >> 2;
    float acc[8];
#pragma unroll
    for (int k = 0; k < 8; k++) acc[k] = 0.f;
    float dsum[8];
#pragma unroll
    for (int j = 0; j < 8; j++) dsum[j] = 0.f;

    for (int base = beg; base < end; base += 32) {
        int i = base + lane;
        int s = -1;
        float w[8];
        if (i < end) {
            s = csrc[i];
#pragma unroll
            for (int j = 0; j < 8; j++) {
                float lg = es[s * 8 + j] + edn[j];
                lg = (lg > 0.f) ? lg : NEG_SLOPE * lg;
                w[j] = __expf(lg - mh[j]);
                dsum[j] += w[j];
            }
        } else {
#pragma unroll
            for (int j = 0; j < 8; j++) w[j] = 0.f;
        }
        ss[warp][lane] = s;
#pragma unroll
        for (int j = 0; j < 8; j++) sw[warp][lane][j] = w[j];
        __syncwarp();
        int cnt = min(32, end - base);
        if (cnt > 0) {
            // 1-deep prefetch pipeline over the serial edge loop
            uint4 hv = *reinterpret_cast<const uint4*>(
                &h[(size_t)ss[warp][0] * C_DIM + lane * 8]);
            for (int e2 = 0; e2 < cnt; e2++) {
                uint4 cur = hv;
                if (e2 + 1 < cnt) {
                    hv = *reinterpret_cast<const uint4*>(
                        &h[(size_t)ss[warp][e2 + 1] * C_DIM + lane * 8]);
                }
                float we = sw[warp][e2][head];
                float2 f0 = __bfloat1622float2(*reinterpret_cast<__nv_bfloat162*>(&cur.x));
                float2 f1 = __bfloat1622float2(*reinterpret_cast<__nv_bfloat162*>(&cur.y));
                float2 f2 = __bfloat1622float2(*reinterpret_cast<__nv_bfloat162*>(&cur.z));
                float2 f3 = __bfloat1622float2(*reinterpret_cast<__nv_bfloat162*>(&cur.w));
                acc[0] += we * f0.x; acc[1] += we * f0.y;
                acc[2] += we * f1.x; acc[3] += we * f1.y;
                acc[4] += we * f2.x; acc[5] += we * f2.y;
                acc[6] += we * f3.x; acc[7] += we * f3.y;
            }
        }
        __syncwarp();
    }
#pragma unroll
    for (int off = 16; off > 0; off >>= 1)
#pragma unroll
        for (int j = 0; j < 8; j++) dsum[j] += __shfl_xor_sync(0xFFFFFFFFu, dsum[j], off);

    float inv = 1.0f / (dsum[head] + 1e-16f);
    float mid[8];
#pragma unroll
    for (int j = 0; j < 8; j++) mid[j] = fmaxf(acc[j] * inv, 0.f);

    // memory cross-attention
    float s[MS_SLOTS];
#pragma unroll
    for (int m = 0; m < MS_SLOTS; m++) {
        const float* pr = &sp[m][lane * 8];
        float p = mid[0] * pr[0] + mid[1] * pr[1] + mid[2] * pr[2] + mid[3] * pr[3]
                + mid[4] * pr[4] + mid[5] * pr[5] + mid[6] * pr[6] + mid[7] * pr[7];
#pragma unroll
        for (int off = 16; off > 0; off >>= 1) p += __shfl_xor_sync(0xFFFFFFFFu, p, off);
        s[m] = p * 0.0625f;
    }
    float mx = s[0];
#pragma unroll
    for (int m = 1; m < MS_SLOTS; m++) mx = fmaxf(mx, s[m]);
    float sum = 0.f;
#pragma unroll
    for (int m = 0; m < MS_SLOTS; m++) { s[m] = __expf(s[m] - mx); sum += s[m]; }
    float invs = 1.0f / sum;

    const float4* xp = reinterpret_cast<const float4*>(&xin[(size_t)n * C_DIM + lane * 8]);
    float4 x0 = xp[0], x1 = xp[1];
    float o[8] = {mid[0] + x0.x, mid[1] + x0.y, mid[2] + x0.z, mid[3] + x0.w,
                  mid[4] + x1.x, mid[5] + x1.y, mid[6] + x1.z, mid[7] + x1.w};
#pragma unroll
    for (int m = 0; m < MS_SLOTS; m++) {
        float a = s[m] * invs;
        const float4* vp = reinterpret_cast<const float4*>(&sv[m][lane * 8]);
        float4 v0 = vp[0], v1 = vp[1];
        o[0] += a * v0.x; o[1] += a * v0.y; o[2] += a * v0.z; o[3] += a * v0.w;
        o[4] += a * v1.x; o[5] += a * v1.y; o[6] += a * v1.z; o[7] += a * v1.w;
    }
#pragma unroll
    for (int j = 0; j < 8; j++) o[j] = fmaxf(o[j], 0.f);
    float4* op = reinterpret_cast<float4*>(&node_out[(size_t)n * C_DIM + lane * 8]);
    op[0] = make_float4(o[0], o[1], o[2], o[3]);
    op[1] = make_float4(o[4], o[5], o[6], o[7]);
    if (tpn) {
        const float4* tp = reinterpret_cast<const float4*>(&tpn[(size_t)n * TP_LD + lane * 8]);
        float4 t0 = tp[0], t1 = tp[1];
        __nv_bfloat162 b0 = __floats2bfloat162_rn(o[0] + t0.x, o[1] + t0.y);
        __nv_bfloat162 b1 = __floats2bfloat162_rn(o[2] + t0.z, o[3] + t0.w);
        __nv_bfloat162 b2 = __floats2bfloat162_rn(o[4] + t1.x, o[5] + t1.y);
        __nv_bfloat162 b3 = __floats2bfloat162_rn(o[6] + t1.z, o[7] + t1.w);
        uint4 pk;
        pk.x = *reinterpret_cast<uint32_t*>(&b0);
        pk.y = *reinterpret_cast<uint32_t*>(&b1);
        pk.z = *reinterpret_cast<uint32_t*>(&b2);
        pk.w = *reinterpret_cast<uint32_t*>(&b3);
        *reinterpret_cast<uint4*>(&xt_out[(size_t)n * C_DIM + lane * 8]) = pk;
    }
}

// ---------------- pooling + final projection ----------------------------------
__global__ void pool_kernel(const float* __restrict__ node, float* __restrict__ pool) {
    int c = threadIdx.x;
    float acc = 0.f;
    for (int r = blockIdx.x; r < N_NODES; r += gridDim.x) acc += node[(size_t)r * C_DIM + c];
    atomicAdd(&pool[c], acc);
}

__global__ void final_kernel(const float* __restrict__ pool, const float* __restrict__ mem,
                             const float* __restrict__ Wc, const float* __restrict__ bc,
                             float* __restrict__ out) {
    __shared__ float s0[512], s1[512];
    int i = threadIdx.x;
    float val = 0.f;
    if (i < C_DIM) {
        val = pool[i] * (1.0f / (float)N_NODES);
    } else if (i < C_DIM + MD_DIM) {
        int t = i - C_DIM;
        float a = 0.f;
#pragma unroll
        for (int m = 0; m < MS_SLOTS; m++) a += mem[m * MD_DIM + t];
        val = a * (1.0f / (float)MS_SLOTS);
    }
    float c0 = 0.f, c1 = 0.f;
    if (i < C_DIM + MD_DIM) { c0 = val * Wc[i * 2 + 0]; c1 = val * Wc[i * 2 + 1]; }
    s0[i] = c0; s1[i] = c1;
    __syncthreads();
    for (int st = 256; st > 0; st >>= 1) {
        if (i < st) { s0[i] += s0[i + st]; s1[i] += s1[i + st]; }
        __syncthreads();
    }
    if (i == 0) { out[0] = s0[0] + bc[0]; out[1] = s1[0] + bc[1]; }
}

// ---------------- host launch -------------------------------------------------
static void* getsym(const void* symbol) {
    void* p = nullptr;
    cudaGetSymbolAddress(&p, symbol);
    return p;
}

extern "C" void kernel_launch(void* const* d_in, const int* in_sizes, int n_in,
                              void* d_out, int out_size) {
    const float* x    = (const float*)d_in[0];
    const int*   ei   = (const int*)  d_in[1];
    const float* te   = (const float*)d_in[2];
    const float* Wi   = (const float*)d_in[3];
    const float* bi   = (const float*)d_in[4];
    const float* Wg   = (const float*)d_in[5];
    const float* a_s  = (const float*)d_in[6];
    const float* a_d  = (const float*)d_in[7];
    const float* Wt   = (const float*)d_in[8];
    const float* Wq   = (const float*)d_in[9];
    const float* Wk   = (const float*)d_in[10];
    const float* Wv   = (const float*)d_in[11];
    const float* mem  = (const float*)d_in[12];
    const float* Wc   = (const float*)d_in[13];
    const float* bc   = (const float*)d_in[14];
    float* out = (float*)d_out;

    float* nodeA = (float*)getsym(g_nodeA);
    float* nodeB = (float*)getsym(g_nodeB);
    __nv_bfloat16* xt  = (__nv_bfloat16*)getsym(g_xt);
    __nv_bfloat16* hbf = (__nv_bfloat16*)getsym(g_hbf);
    __nv_bfloat16* xbf = (__nv_bfloat16*)getsym(g_xbf);
    __nv_bfloat16* tebf= (__nv_bfloat16*)getsym(g_tebf);
    float* tpall = (float*)getsym(g_tpall);
    float* Wtall = (float*)getsym(g_Wtall);
    uint32_t* Wipk = (uint32_t*)getsym(g_Wipk);
    uint32_t* Wtpk = (uint32_t*)getsym(g_Wtpk);
    uint32_t* Wgpk = (uint32_t*)getsym(g_Wgpk);
    float* esb   = (float*)getsym(g_es);
    float* edb   = (float*)getsym(g_ed);
    float* kall  = (float*)getsym(g_kall);
    float* vall  = (float*)getsym(g_vall);
    float* Ptall = (float*)getsym(g_Ptall);
    float* pool  = (float*)getsym(g_pool);
    int* cnt     = (int*)getsym(g_cnt);
    int* rowptr  = (int*)getsym(g_rowptr);
    int* cursor  = (int*)getsym(g_cursor);
    int* csrc    = (int*)getsym(g_csrc);

    const int* src = ei;
    const int* dst = ei + N_EDGES;

    const int smem_bytes = SMEM_U32 * 4;   // 86016
    static bool attr_set = false;
    if (!attr_set) {
        cudaFuncSetAttribute(bgemm_kernel, cudaFuncAttributeMaxDynamicSharedMemorySize, smem_bytes);
        attr_set = true;
    }

    // CSR build
    zero_int_kernel<<<(N_NODES + 255) / 256, 256>>>(cnt, N_NODES);
    count_kernel<<<(N_EDGES + 255) / 256, 256>>>(dst, cnt);
    scan_kernel<<<1, 1024>>>(cnt, rowptr, cursor);
    scatter_kernel<<<(N_EDGES + 255) / 256, 256>>>(src, dst, cursor, csrc);

    // conversions + packing
    f2bf_kernel<<<(N_NODES * 128 + 255) / 256, 256>>>(x, xbf, N_NODES * 128);
    f2bf_kernel<<<(N_NODES * T_DIM + 255) / 256, 256>>>(te, tebf, N_NODES * T_DIM);
    reshape_wt_kernel<<<(L_LAYERS * T_DIM * C_DIM + 255) / 256, 256>>>(Wt, Wtall);
    pack_w_kernel<<<((T_DIM / 2) * TP_LD + 255) / 256, 256>>>(Wtall, Wtpk, T_DIM, TP_LD);
    pack_w_kernel<<<((128 / 2) * C_DIM + 255) / 256, 256>>>(Wi, Wipk, 128, C_DIM);
    for (int l = 0; l < L_LAYERS; l++)
        pack_w_kernel<<<((C_DIM / 2) * C_DIM + 255) / 256, 256>>>(
            Wg + (size_t)l * C_DIM * C_DIM, Wgpk + (size_t)l * (C_DIM / 2) * C_DIM,
            C_DIM, C_DIM);

    // k/v/Pt precompute
    kvall_kernel<<<L_LAYERS * MS_SLOTS, 256>>>(mem, Wk, Wv, kall, vall);
    ptall_kernel<<<L_LAYERS * MS_SLOTS, 256>>>(Wq, kall, Ptall);

    // tpall = te @ Wtall  [20000 x 1280]
    dim3 tp_grid(TP_LD / TBN, N_NODES / TBM);     // (10, 125)
    bgemm_kernel<<<tp_grid, 256, smem_bytes>>>(tebf, Wtpk, nullptr, nullptr, 0, nullptr,
                                               nullptr, nullptr, nullptr, nullptr,
                                               tpall, N_NODES, TP_LD, T_DIM, 0);

    dim3 gemm_grid(C_DIM / TBN, N_NODES / TBM);   // (2, 125)

    // input projection: nodeA = relu(x @ Wi + bi); xt(bf16) = nodeA + tpall[:,0:256]
    bgemm_kernel<<<gemm_grid, 256, smem_bytes>>>(xbf, Wipk, bi, tpall, TP_LD, xt,
                                                 nullptr, nullptr, nullptr, nullptr,
                                                 nodeA, N_NODES, C_DIM, 128, 1);

    float* nin = nodeA;
    float* nout = nodeB;
    for (int l = 0; l < L_LAYERS; l++) {
        bgemm_kernel<<<gemm_grid, 256, smem_bytes>>>(xt, Wgpk + (size_t)l * (C_DIM / 2) * C_DIM,
                                                     nullptr, nullptr, 0, nullptr,
                                                     a_s + l * H_HEADS * D_HEAD,
                                                     a_d + l * H_HEADS * D_HEAD, esb, edb,
                                                     hbf, N_NODES, C_DIM, C_DIM, 3);
        const float* tpn = (l + 1 < L_LAYERS) ? (tpall + (size_t)(l + 1) * C_DIM) : nullptr;
        edge_mem_kernel<<<(N_NODES + 7) / 8, 256>>>(hbf, rowptr, csrc, esb, edb,
                                                    Ptall + (size_t)l * MS_SLOTS * C_DIM,
                                                    vall + (size_t)l * MS_SLOTS * C_DIM,
                                                    nin, tpn, nout, xt);
        float* tmp = nin; nin = nout; nout = tmp;
    }

    zero_float_kernel<<<1, 256>>>(pool, C_DIM);
    pool_kernel<<<148, 256>>>(nin, pool);
    final_kernel<<<1, 512>>>(pool, mem, Wc, bc, out);
}